// round 12
// baseline (speedup 1.0000x reference)
#include <cuda_runtime.h>
#include <cuda_bf16.h>
#include <cstdint>

// Problem constants
#define BB 4
#define SS 2048
#define DD 1024
#define HH 16
#define DKK 64
#define MROWS (BB*SS)          // 8192

// ---------------------------------------------------------------------------
// Scratch (device globals — no allocations allowed)
// ---------------------------------------------------------------------------
__device__ __nv_bfloat16 g_qh[MROWS*DD], g_ql[MROWS*DD];   // Q proj out (pre-scaled 1/8)
__device__ __nv_bfloat16 g_kh[MROWS*DD], g_kl[MROWS*DD];   // K proj out
__device__ __nv_bfloat16 g_vh[MROWS*DD], g_vl[MROWS*DD];   // V proj out
__device__ __nv_bfloat16 g_ah[MROWS*DD], g_al[MROWS*DD];   // GEMM-A splits / attn out
__device__ __nv_bfloat16 g_wh[DD*DD],   g_wl[DD*DD];       // weight splits

// ---------------------------------------------------------------------------
// Helpers
// ---------------------------------------------------------------------------
__device__ __forceinline__ uint32_t smem_u32(const void* p) {
    uint32_t a;
    asm("{ .reg .u64 t; cvta.to.shared.u64 t, %1; cvt.u32.u64 %0, t; }" : "=r"(a) : "l"(p));
    return a;
}
#define SWZ128(o) ((o) ^ (((o) >> 3) & 0x70))

#define CP_ASYNC16(dst, src) \
    asm volatile("cp.async.cg.shared.global [%0], [%1], 16;" :: "r"(dst), "l"(src))
#define CP_COMMIT()  asm volatile("cp.async.commit_group;" ::: "memory")
#define CP_WAIT0()   asm volatile("cp.async.wait_group 0;" ::: "memory")

__device__ __forceinline__ void ldsm_x4(uint32_t* r, uint32_t addr) {
    asm volatile("ldmatrix.sync.aligned.m8n8.x4.shared.b16 {%0,%1,%2,%3}, [%4];"
        : "=r"(r[0]), "=r"(r[1]), "=r"(r[2]), "=r"(r[3]) : "r"(addr));
}
__device__ __forceinline__ void ldsm_x2(uint32_t* r, uint32_t addr) {
    asm volatile("ldmatrix.sync.aligned.m8n8.x2.shared.b16 {%0,%1}, [%2];"
        : "=r"(r[0]), "=r"(r[1]) : "r"(addr));
}
__device__ __forceinline__ void ldsm_x2t(uint32_t* r, uint32_t addr) {
    asm volatile("ldmatrix.sync.aligned.m8n8.x2.trans.shared.b16 {%0,%1}, [%2];"
        : "=r"(r[0]), "=r"(r[1]) : "r"(addr));
}
__device__ __forceinline__ void mma16816(float* d, const uint32_t* a, const uint32_t* b) {
    asm volatile("mma.sync.aligned.m16n8k16.row.col.f32.bf16.bf16.f32 "
        "{%0,%1,%2,%3}, {%4,%5,%6,%7}, {%8,%9}, {%0,%1,%2,%3};"
        : "+f"(d[0]), "+f"(d[1]), "+f"(d[2]), "+f"(d[3])
        : "r"(a[0]), "r"(a[1]), "r"(a[2]), "r"(a[3]), "r"(b[0]), "r"(b[1]));
}
__device__ __forceinline__ uint32_t packbf2(float x, float y) {
    __nv_bfloat162 t = __floats2bfloat162_rn(x, y);
    return *reinterpret_cast<uint32_t*>(&t);
}

// ---------------------------------------------------------------------------
// Split fp32 -> (bf16 hi, bf16 lo) with residual capture
// ---------------------------------------------------------------------------
__global__ __launch_bounds__(256) void split_kernel(
    const float* __restrict__ x, __nv_bfloat16* __restrict__ hi,
    __nv_bfloat16* __restrict__ lo, int n4)
{
    int i = blockIdx.x * 256 + threadIdx.x;
    if (i >= n4) return;
    float4 v = reinterpret_cast<const float4*>(x)[i];
    __nv_bfloat162 h0 = __floats2bfloat162_rn(v.x, v.y);
    __nv_bfloat162 h1 = __floats2bfloat162_rn(v.z, v.w);
    float r0 = v.x - __low2float(h0), r1 = v.y - __high2float(h0);
    float r2 = v.z - __low2float(h1), r3 = v.w - __high2float(h1);
    __nv_bfloat162* hp = reinterpret_cast<__nv_bfloat162*>(hi);
    __nv_bfloat162* lp = reinterpret_cast<__nv_bfloat162*>(lo);
    hp[2*i]   = h0;
    hp[2*i+1] = h1;
    lp[2*i]   = __floats2bfloat162_rn(r0, r1);
    lp[2*i+1] = __floats2bfloat162_rn(r2, r3);
}

// ---------------------------------------------------------------------------
// HMMA bf16x3 GEMM (NT): acc = sum_k A[i,k]*W[j,k]; out = (acc + bias[j])*scale
// Output either fp32 C, or bf16 hi/lo pair (Ch,Cl).
// CTA tile 128x128, K chunk 64, SW128 smem, cp.async double-buffered.
// 8 warps in 2(m) x 4(n); warp tile 64x32 via m16n8k16.
// ---------------------------------------------------------------------------
#define TILE_BYTES 16384               // 128 rows x 128B
#define BUF_BYTES  (4*TILE_BYTES)      // Ah,Al,Bh,Bl
#define GEMM_SMEM  (1024 + 2*BUF_BYTES)

__global__ __launch_bounds__(256, 1) void gemm_tc_kernel(
    const __nv_bfloat16* __restrict__ Ah, const __nv_bfloat16* __restrict__ Al,
    const __nv_bfloat16* __restrict__ Bh, const __nv_bfloat16* __restrict__ Bl,
    const float* __restrict__ bias, float* __restrict__ C,
    __nv_bfloat16* __restrict__ Ch, __nv_bfloat16* __restrict__ Cl, float scale)
{
    extern __shared__ char smem[];
    const uint32_t sbase = (smem_u32(smem) + 1023u) & ~1023u;
    const int tid = threadIdx.x;
    const int wid = tid >> 5;
    const int lid = tid & 31;
    const int wm  = wid >> 2;          // 0..1
    const int wn  = wid & 3;           // 0..3
    const int nBase = blockIdx.x * 128;
    const int mBase = blockIdx.y * 128;

    const uint4* srcs[4] = {
        reinterpret_cast<const uint4*>(Ah) + (size_t)mBase * 128,
        reinterpret_cast<const uint4*>(Al) + (size_t)mBase * 128,
        reinterpret_cast<const uint4*>(Bh) + (size_t)nBase * 128,
        reinterpret_cast<const uint4*>(Bl) + (size_t)nBase * 128
    };

    auto load_chunk = [&](int ch, int buf) {
        const int kq = ch * 8;
        const uint32_t bufAddr = sbase + buf * BUF_BYTES;
#pragma unroll
        for (int t = 0; t < 16; t++) {
            const int tile = t >> 2;
            const int i = tid + (t & 3) * 256;
            const int r = i >> 3, c = i & 7;
            const uint4* src = srcs[tile] + (size_t)r * 128 + kq + c;
            uint32_t dst = bufAddr + tile * TILE_BYTES + SWZ128(r * 128 + c * 16);
            CP_ASYNC16(dst, src);
        }
        CP_COMMIT();
    };

    float acc[4][4][4];
#pragma unroll
    for (int mt = 0; mt < 4; mt++)
#pragma unroll
        for (int nt = 0; nt < 4; nt++)
#pragma unroll
            for (int r = 0; r < 4; r++) acc[mt][nt][r] = 0.f;

    load_chunk(0, 0);
    CP_WAIT0();
    __syncthreads();

    const int aRow = wm * 64 + (lid & 15);
    const int aColH = (lid >> 4) * 16;
    const int bRow = wn * 32 + (lid & 7);
    const int bColH = ((lid >> 3) & 1) * 16;

#pragma unroll 1
    for (int ch = 0; ch < 16; ch++) {
        const int cur = ch & 1;
        if (ch < 15) load_chunk(ch + 1, cur ^ 1);

        const uint32_t bufAddr = sbase + cur * BUF_BYTES;
        const uint32_t aH = bufAddr;
        const uint32_t aL = bufAddr + TILE_BYTES;
        const uint32_t bH = bufAddr + 2 * TILE_BYTES;
        const uint32_t bL = bufAddr + 3 * TILE_BYTES;

#pragma unroll
        for (int ks = 0; ks < 4; ks++) {
            const int kByte = ks * 32;
            uint32_t ah[4][4], al[4][4], bh[4][2], bl[4][2];
#pragma unroll
            for (int mt = 0; mt < 4; mt++) {
                uint32_t off = SWZ128((aRow + mt * 16) * 128 + kByte + aColH);
                ldsm_x4(ah[mt], aH + off);
                ldsm_x4(al[mt], aL + off);
            }
#pragma unroll
            for (int nt = 0; nt < 4; nt++) {
                uint32_t off = SWZ128((bRow + nt * 8) * 128 + kByte + bColH);
                ldsm_x2(bh[nt], bH + off);
                ldsm_x2(bl[nt], bL + off);
            }
#pragma unroll
            for (int mt = 0; mt < 4; mt++)
#pragma unroll
                for (int nt = 0; nt < 4; nt++) {
                    mma16816(acc[mt][nt], ah[mt], bh[nt]);
                    mma16816(acc[mt][nt], ah[mt], bl[nt]);
                    mma16816(acc[mt][nt], al[mt], bh[nt]);
                }
        }

        if (ch < 15) CP_WAIT0();
        __syncthreads();
    }

    // Epilogue
    const int erow = mBase + wm * 64 + (lid >> 2);
    const int ecolBase = nBase + wn * 32 + 2 * (lid & 3);
#pragma unroll
    for (int nt = 0; nt < 4; nt++) {
        const int col = ecolBase + nt * 8;
        const float b0 = __ldg(bias + col), b1 = __ldg(bias + col + 1);
#pragma unroll
        for (int mt = 0; mt < 4; mt++) {
            const int r0 = erow + mt * 16;
            float v0 = (acc[mt][nt][0] + b0) * scale;
            float v1 = (acc[mt][nt][1] + b1) * scale;
            float v2 = (acc[mt][nt][2] + b0) * scale;
            float v3 = (acc[mt][nt][3] + b1) * scale;
            if (C) {
                *reinterpret_cast<float2*>(C + (size_t)r0 * DD + col)       = make_float2(v0, v1);
                *reinterpret_cast<float2*>(C + (size_t)(r0 + 8) * DD + col) = make_float2(v2, v3);
            } else {
                __nv_bfloat162 h0 = __floats2bfloat162_rn(v0, v1);
                __nv_bfloat162 h1 = __floats2bfloat162_rn(v2, v3);
                *reinterpret_cast<__nv_bfloat162*>(Ch + (size_t)r0 * DD + col)       = h0;
                *reinterpret_cast<__nv_bfloat162*>(Ch + (size_t)(r0 + 8) * DD + col) = h1;
                *reinterpret_cast<__nv_bfloat162*>(Cl + (size_t)r0 * DD + col) =
                    __floats2bfloat162_rn(v0 - __low2float(h0), v1 - __high2float(h0));
                *reinterpret_cast<__nv_bfloat162*>(Cl + (size_t)(r0 + 8) * DD + col) =
                    __floats2bfloat162_rn(v2 - __low2float(h1), v3 - __high2float(h1));
            }
        }
    }
}

// ---------------------------------------------------------------------------
// MMA flash attention. Q pre-scaled by 1/8. All operands bf16 hi/lo in
// [B,S,D] layout (head h = cols h*64..+63). Output -> (Oh,Ol) bf16 hi/lo.
// CTA: 128 query rows x one (b,h); 8 warps x 16 rows; BK=32 keys/iter.
// scores = Qh*Kh + Qh*Kl + Ql*Kh ; PV = Ph*Vh + Ph*Vl + Pl*Vh (fp32 acc).
// P A-fragments come directly from score accumulators (layout identity).
// ---------------------------------------------------------------------------
#define KV_BYTES 16384                 // Kh,Kl,Vh,Vl 32x128B each
#define ATT_SMEM (32768 + 2*KV_BYTES + 1024)

__global__ __launch_bounds__(256, 2) void attn_mma_kernel(
    const __nv_bfloat16* __restrict__ Qh, const __nv_bfloat16* __restrict__ Ql,
    const __nv_bfloat16* __restrict__ Kh, const __nv_bfloat16* __restrict__ Kl,
    const __nv_bfloat16* __restrict__ Vh, const __nv_bfloat16* __restrict__ Vl,
    __nv_bfloat16* __restrict__ Oh, __nv_bfloat16* __restrict__ Ol)
{
    extern __shared__ char smem[];
    const uint32_t sb = (smem_u32(smem) + 1023u) & ~1023u;
    const int tid = threadIdx.x;
    const int wid = tid >> 5;
    const int lid = tid & 31;
    const int bh  = blockIdx.y;
    const int b   = bh >> 4, h = bh & 15;
    const int qBase = blockIdx.x * 128;

    const uint32_t QH_OFF = 0, QL_OFF = 16384, KV_OFF = 32768;
    const size_t qOrg = (size_t)(b * SS + qBase) * DD + h * DKK;   // Q tile origin (elems)
    const size_t kOrg = (size_t)(b * SS) * DD + h * DKK;           // K/V batch origin

    // ---- stage Q (hi/lo) : 2 x 128 rows x 8 chunks of 16B ----
    {
        const int idx = tid & 1023;        // placeholder to keep pattern clear
        (void)idx;
#pragma unroll
        for (int j = 0; j < 8; j++) {
            int i  = tid + j * 256;        // 0..2047
            int sp = i >> 10;              // 0=hi 1=lo
            int r  = (i & 1023) >> 3;
            int c  = i & 7;
            const __nv_bfloat16* src = (sp ? Ql : Qh) + qOrg + (size_t)r * DD + c * 8;
            uint32_t dst = sb + (sp ? QL_OFF : QH_OFF) + SWZ128(r * 128 + c * 16);
            CP_ASYNC16(dst, src);
        }
    }
    // ---- K/V tile loader: 32 keys x 64 dims, 4 tiles (Kh,Kl,Vh,Vl) ----
    const __nv_bfloat16* kvsrc[4] = { Kh, Kl, Vh, Vl };
    auto load_kv = [&](int t, int buf) {
        const int r = tid >> 3, c = tid & 7;             // r 0..31, c 0..7
        const size_t g = kOrg + (size_t)(t * 32 + r) * DD + c * 8;
        const uint32_t dstb = sb + KV_OFF + buf * KV_BYTES + SWZ128(r * 128 + c * 16);
#pragma unroll
        for (int tile = 0; tile < 4; tile++)
            CP_ASYNC16(dstb + tile * 4096, kvsrc[tile] + g);
        CP_COMMIT();
    };

    load_kv(0, 0);
    CP_WAIT0();
    __syncthreads();

    // ---- Q fragments (held in regs for whole kernel) ----
    uint32_t qfh[4][4], qfl[4][4];
    {
        const int aRow = wid * 16 + (lid & 15);
        const int aColH = (lid >> 4) * 16;
#pragma unroll
        for (int ks = 0; ks < 4; ks++) {
            uint32_t off = SWZ128(aRow * 128 + ks * 32 + aColH);
            ldsm_x4(qfh[ks], sb + QH_OFF + off);
            ldsm_x4(qfl[ks], sb + QL_OFF + off);
        }
    }

    float o[8][4];
#pragma unroll
    for (int nt = 0; nt < 8; nt++)
#pragma unroll
        for (int r = 0; r < 4; r++) o[nt][r] = 0.f;
    float m0 = -1e30f, m1 = -1e30f, l0 = 0.f, l1 = 0.f;

    // fragment address components
    const uint32_t kFragBase = (lid & 7) * 128 + ((lid >> 3) & 1) * 16;       // + nt*1024 + ks*32
    const uint32_t vFragRow  = ((lid & 7) + 8 * ((lid >> 3) & 1)) * 128;      // + ks*2048 + nt*16

#pragma unroll 1
    for (int t = 0; t < SS / 32; t++) {
        const int cur = t & 1;
        if (t < SS / 32 - 1) load_kv(t + 1, cur ^ 1);

        const uint32_t kb = sb + KV_OFF + cur * KV_BYTES;

        // ---- scores: m16 x n32 x k64, bf16x3 ----
        float s[4][4];
#pragma unroll
        for (int nt = 0; nt < 4; nt++)
#pragma unroll
            for (int r = 0; r < 4; r++) s[nt][r] = 0.f;
#pragma unroll
        for (int ks = 0; ks < 4; ks++) {
#pragma unroll
            for (int nt = 0; nt < 4; nt++) {
                uint32_t kbh[2], kbl[2];
                uint32_t off = SWZ128(nt * 1024 + kFragBase + ks * 32);
                ldsm_x2(kbh, kb + off);            // Kh tile @ +0
                ldsm_x2(kbl, kb + 4096 + off);     // Kl tile
                mma16816(s[nt], qfh[ks], kbh);
                mma16816(s[nt], qfh[ks], kbl);
                mma16816(s[nt], qfl[ks], kbh);
            }
        }

        // ---- online softmax (rows r=lid>>2 and r+8; cols across lanes lid&3) ----
        float t0 = -1e30f, t1 = -1e30f;
#pragma unroll
        for (int nt = 0; nt < 4; nt++) {
            t0 = fmaxf(t0, fmaxf(s[nt][0], s[nt][1]));
            t1 = fmaxf(t1, fmaxf(s[nt][2], s[nt][3]));
        }
        t0 = fmaxf(t0, __shfl_xor_sync(0xffffffffu, t0, 1));
        t0 = fmaxf(t0, __shfl_xor_sync(0xffffffffu, t0, 2));
        t1 = fmaxf(t1, __shfl_xor_sync(0xffffffffu, t1, 1));
        t1 = fmaxf(t1, __shfl_xor_sync(0xffffffffu, t1, 2));
        const float mn0 = fmaxf(m0, t0), mn1 = fmaxf(m1, t1);
        const float c0 = __expf(m0 - mn0), c1 = __expf(m1 - mn1);
        m0 = mn0; m1 = mn1;

        uint32_t aPh[2][4], aPl[2][4];
        float rs0 = 0.f, rs1 = 0.f;
#pragma unroll
        for (int nt = 0; nt < 4; nt++) {
            float p0 = __expf(s[nt][0] - m0);
            float p1 = __expf(s[nt][1] - m0);
            float p2 = __expf(s[nt][2] - m1);
            float p3 = __expf(s[nt][3] - m1);
            rs0 += p0 + p1; rs1 += p2 + p3;
            const int ks = nt >> 1, pos = (nt & 1) * 2;
            __nv_bfloat162 hA = __floats2bfloat162_rn(p0, p1);
            __nv_bfloat162 hB = __floats2bfloat162_rn(p2, p3);
            aPh[ks][pos]     = *reinterpret_cast<uint32_t*>(&hA);
            aPh[ks][pos + 1] = *reinterpret_cast<uint32_t*>(&hB);
            aPl[ks][pos]     = packbf2(p0 - __low2float(hA), p1 - __high2float(hA));
            aPl[ks][pos + 1] = packbf2(p2 - __low2float(hB), p3 - __high2float(hB));
        }
        rs0 += __shfl_xor_sync(0xffffffffu, rs0, 1);
        rs0 += __shfl_xor_sync(0xffffffffu, rs0, 2);
        rs1 += __shfl_xor_sync(0xffffffffu, rs1, 1);
        rs1 += __shfl_xor_sync(0xffffffffu, rs1, 2);
        l0 = l0 * c0 + rs0;
        l1 = l1 * c1 + rs1;

#pragma unroll
        for (int nt = 0; nt < 8; nt++) {
            o[nt][0] *= c0; o[nt][1] *= c0;
            o[nt][2] *= c1; o[nt][3] *= c1;
        }

        // ---- PV: m16 x n64 x k32, bf16x3 (V via ldmatrix.trans) ----
#pragma unroll
        for (int ks = 0; ks < 2; ks++) {
#pragma unroll
            for (int nt = 0; nt < 8; nt++) {
                uint32_t vbh[2], vbl[2];
                uint32_t off = SWZ128(ks * 2048 + vFragRow + nt * 16);
                ldsm_x2t(vbh, kb + 8192 + off);     // Vh tile
                ldsm_x2t(vbl, kb + 12288 + off);    // Vl tile
                mma16816(o[nt], aPh[ks], vbh);
                mma16816(o[nt], aPh[ks], vbl);
                mma16816(o[nt], aPl[ks], vbh);
            }
        }

        CP_WAIT0();
        __syncthreads();
    }

    // ---- epilogue: normalize, split to bf16 hi/lo, write [B,S,D] ----
    const float i0 = 1.f / l0, i1 = 1.f / l1;
    const size_t row0 = (size_t)(b * SS + qBase + wid * 16 + (lid >> 2));
    const int colBase = h * DKK + 2 * (lid & 3);
#pragma unroll
    for (int nt = 0; nt < 8; nt++) {
        const int col = colBase + nt * 8;
        float v0 = o[nt][0] * i0, v1 = o[nt][1] * i0;
        float v2 = o[nt][2] * i1, v3 = o[nt][3] * i1;
        __nv_bfloat162 h0 = __floats2bfloat162_rn(v0, v1);
        __nv_bfloat162 h1 = __floats2bfloat162_rn(v2, v3);
        *reinterpret_cast<__nv_bfloat162*>(Oh + row0 * DD + col)       = h0;
        *reinterpret_cast<__nv_bfloat162*>(Oh + (row0 + 8) * DD + col) = h1;
        *reinterpret_cast<__nv_bfloat162*>(Ol + row0 * DD + col) =
            __floats2bfloat162_rn(v0 - __low2float(h0), v1 - __high2float(h0));
        *reinterpret_cast<__nv_bfloat162*>(Ol + (row0 + 8) * DD + col) =
            __floats2bfloat162_rn(v2 - __low2float(h1), v3 - __high2float(h1));
    }
}

// ---------------------------------------------------------------------------
// kernel_launch
// ---------------------------------------------------------------------------
extern "C" void kernel_launch(void* const* d_in, const int* in_sizes, int n_in,
                              void* d_out, int out_size)
{
    const float* query = (const float*)d_in[0];
    const float* key   = (const float*)d_in[1];
    const float* value = (const float*)d_in[2];
    const float* Wq    = (const float*)d_in[3];
    const float* bq    = (const float*)d_in[4];
    const float* Wk    = (const float*)d_in[5];
    const float* bk    = (const float*)d_in[6];
    const float* Wv    = (const float*)d_in[7];
    const float* bv    = (const float*)d_in[8];
    const float* Wo    = (const float*)d_in[9];
    const float* bo    = (const float*)d_in[10];
    float* out = (float*)d_out;

    __nv_bfloat16 *qh, *ql, *kh, *kl, *vh, *vl, *ah, *al, *wh, *wl;
    cudaGetSymbolAddress((void**)&qh, g_qh);
    cudaGetSymbolAddress((void**)&ql, g_ql);
    cudaGetSymbolAddress((void**)&kh, g_kh);
    cudaGetSymbolAddress((void**)&kl, g_kl);
    cudaGetSymbolAddress((void**)&vh, g_vh);
    cudaGetSymbolAddress((void**)&vl, g_vl);
    cudaGetSymbolAddress((void**)&ah, g_ah);
    cudaGetSymbolAddress((void**)&al, g_al);
    cudaGetSymbolAddress((void**)&wh, g_wh);
    cudaGetSymbolAddress((void**)&wl, g_wl);

    cudaFuncSetAttribute(gemm_tc_kernel,
                         cudaFuncAttributeMaxDynamicSharedMemorySize, GEMM_SMEM);
    cudaFuncSetAttribute(attn_mma_kernel,
                         cudaFuncAttributeMaxDynamicSharedMemorySize, ATT_SMEM);

    const int n4a = MROWS * DD / 4;
    const int n4w = DD * DD / 4;
    dim3 gGrid(DD / 128, MROWS / 128);   // (8, 64)

    // Q projection (scores scale 1/8 folded into Q)
    split_kernel<<<n4a / 256, 256>>>(query, ah, al, n4a);
    split_kernel<<<n4w / 256, 256>>>(Wq, wh, wl, n4w);
    gemm_tc_kernel<<<gGrid, 256, GEMM_SMEM>>>(ah, al, wh, wl, bq, nullptr, qh, ql, 0.125f);
    // K projection
    split_kernel<<<n4a / 256, 256>>>(key, ah, al, n4a);
    split_kernel<<<n4w / 256, 256>>>(Wk, wh, wl, n4w);
    gemm_tc_kernel<<<gGrid, 256, GEMM_SMEM>>>(ah, al, wh, wl, bk, nullptr, kh, kl, 1.0f);
    // V projection
    split_kernel<<<n4a / 256, 256>>>(value, ah, al, n4a);
    split_kernel<<<n4w / 256, 256>>>(Wv, wh, wl, n4w);
    gemm_tc_kernel<<<gGrid, 256, GEMM_SMEM>>>(ah, al, wh, wl, bv, nullptr, vh, vl, 1.0f);

    // Attention -> (ah, al) bf16 hi/lo
    dim3 aGrid(SS / 128, BB * HH);       // (16, 64)
    attn_mma_kernel<<<aGrid, 256, ATT_SMEM>>>(qh, ql, kh, kl, vh, vl, ah, al);

    // Output projection -> fp32 d_out
    split_kernel<<<n4w / 256, 256>>>(Wo, wh, wl, n4w);
    gemm_tc_kernel<<<gGrid, 256, GEMM_SMEM>>>(ah, al, wh, wl, bo, out, nullptr, nullptr, 1.0f);
}

// round 13
// speedup vs baseline: 1.5282x; 1.5282x over previous
#include <cuda_runtime.h>
#include <cuda_bf16.h>
#include <cstdint>

// Problem constants
#define BB 4
#define SS 2048
#define DD 1024
#define HH 16
#define DKK 64
#define MROWS (BB*SS)          // 8192

// ---------------------------------------------------------------------------
// Scratch (device globals — no allocations allowed)
// ---------------------------------------------------------------------------
__device__ __nv_bfloat16 g_qh[MROWS*DD], g_ql[MROWS*DD];   // Q proj out (pre-scaled 1/8)
__device__ __nv_bfloat16 g_kh[MROWS*DD], g_kl[MROWS*DD];   // K proj out
__device__ __nv_bfloat16 g_vh[MROWS*DD], g_vl[MROWS*DD];   // V proj out
__device__ __nv_bfloat16 g_ah[MROWS*DD], g_al[MROWS*DD];   // GEMM-A splits / attn out
__device__ __nv_bfloat16 g_wh[DD*DD],   g_wl[DD*DD];       // weight splits

// ---------------------------------------------------------------------------
// Helpers
// ---------------------------------------------------------------------------
__device__ __forceinline__ uint32_t smem_u32(const void* p) {
    uint32_t a;
    asm("{ .reg .u64 t; cvta.to.shared.u64 t, %1; cvt.u32.u64 %0, t; }" : "=r"(a) : "l"(p));
    return a;
}
#define SWZ128(o) ((o) ^ (((o) >> 3) & 0x70))

#define CP_ASYNC16(dst, src) \
    asm volatile("cp.async.cg.shared.global [%0], [%1], 16;" :: "r"(dst), "l"(src))
#define CP_COMMIT()  asm volatile("cp.async.commit_group;" ::: "memory")
#define CP_WAIT0()   asm volatile("cp.async.wait_group 0;" ::: "memory")

__device__ __forceinline__ void ldsm_x4(uint32_t* r, uint32_t addr) {
    asm volatile("ldmatrix.sync.aligned.m8n8.x4.shared.b16 {%0,%1,%2,%3}, [%4];"
        : "=r"(r[0]), "=r"(r[1]), "=r"(r[2]), "=r"(r[3]) : "r"(addr));
}
__device__ __forceinline__ void ldsm_x2(uint32_t* r, uint32_t addr) {
    asm volatile("ldmatrix.sync.aligned.m8n8.x2.shared.b16 {%0,%1}, [%2];"
        : "=r"(r[0]), "=r"(r[1]) : "r"(addr));
}
__device__ __forceinline__ void ldsm_x2t(uint32_t* r, uint32_t addr) {
    asm volatile("ldmatrix.sync.aligned.m8n8.x2.trans.shared.b16 {%0,%1}, [%2];"
        : "=r"(r[0]), "=r"(r[1]) : "r"(addr));
}
__device__ __forceinline__ void mma16816(float* d, const uint32_t* a, const uint32_t* b) {
    asm volatile("mma.sync.aligned.m16n8k16.row.col.f32.bf16.bf16.f32 "
        "{%0,%1,%2,%3}, {%4,%5,%6,%7}, {%8,%9}, {%0,%1,%2,%3};"
        : "+f"(d[0]), "+f"(d[1]), "+f"(d[2]), "+f"(d[3])
        : "r"(a[0]), "r"(a[1]), "r"(a[2]), "r"(a[3]), "r"(b[0]), "r"(b[1]));
}
__device__ __forceinline__ uint32_t packbf2(float x, float y) {
    __nv_bfloat162 t = __floats2bfloat162_rn(x, y);
    return *reinterpret_cast<uint32_t*>(&t);
}

// ---------------------------------------------------------------------------
// Split fp32 -> (bf16 hi, bf16 lo) with residual capture
// ---------------------------------------------------------------------------
__global__ __launch_bounds__(256) void split_kernel(
    const float* __restrict__ x, __nv_bfloat16* __restrict__ hi,
    __nv_bfloat16* __restrict__ lo, int n4)
{
    int i = blockIdx.x * 256 + threadIdx.x;
    if (i >= n4) return;
    float4 v = reinterpret_cast<const float4*>(x)[i];
    __nv_bfloat162 h0 = __floats2bfloat162_rn(v.x, v.y);
    __nv_bfloat162 h1 = __floats2bfloat162_rn(v.z, v.w);
    float r0 = v.x - __low2float(h0), r1 = v.y - __high2float(h0);
    float r2 = v.z - __low2float(h1), r3 = v.w - __high2float(h1);
    __nv_bfloat162* hp = reinterpret_cast<__nv_bfloat162*>(hi);
    __nv_bfloat162* lp = reinterpret_cast<__nv_bfloat162*>(lo);
    hp[2*i]   = h0;
    hp[2*i+1] = h1;
    lp[2*i]   = __floats2bfloat162_rn(r0, r1);
    lp[2*i+1] = __floats2bfloat162_rn(r2, r3);
}

// ---------------------------------------------------------------------------
// HMMA bf16x3 GEMM (NT): acc = sum_k A[i,k]*W[j,k]; out = (acc + bias[j])*scale
// Output either fp32 C, or bf16 hi/lo pair (Ch,Cl).
// CTA tile 128x128, K chunk 64, SW128 smem, cp.async double-buffered.
// 8 warps in 2(m) x 4(n); warp tile 64x32 via m16n8k16.
// ---------------------------------------------------------------------------
#define TILE_BYTES 16384               // 128 rows x 128B
#define BUF_BYTES  (4*TILE_BYTES)      // Ah,Al,Bh,Bl
#define GEMM_SMEM  (1024 + 2*BUF_BYTES)

__global__ __launch_bounds__(256, 1) void gemm_tc_kernel(
    const __nv_bfloat16* __restrict__ Ah, const __nv_bfloat16* __restrict__ Al,
    const __nv_bfloat16* __restrict__ Bh, const __nv_bfloat16* __restrict__ Bl,
    const float* __restrict__ bias, float* __restrict__ C,
    __nv_bfloat16* __restrict__ Ch, __nv_bfloat16* __restrict__ Cl, float scale)
{
    extern __shared__ char smem[];
    const uint32_t sbase = (smem_u32(smem) + 1023u) & ~1023u;
    const int tid = threadIdx.x;
    const int wid = tid >> 5;
    const int lid = tid & 31;
    const int wm  = wid >> 2;          // 0..1
    const int wn  = wid & 3;           // 0..3
    const int nBase = blockIdx.x * 128;
    const int mBase = blockIdx.y * 128;

    const uint4* srcs[4] = {
        reinterpret_cast<const uint4*>(Ah) + (size_t)mBase * 128,
        reinterpret_cast<const uint4*>(Al) + (size_t)mBase * 128,
        reinterpret_cast<const uint4*>(Bh) + (size_t)nBase * 128,
        reinterpret_cast<const uint4*>(Bl) + (size_t)nBase * 128
    };

    auto load_chunk = [&](int ch, int buf) {
        const int kq = ch * 8;
        const uint32_t bufAddr = sbase + buf * BUF_BYTES;
#pragma unroll
        for (int t = 0; t < 16; t++) {
            const int tile = t >> 2;
            const int i = tid + (t & 3) * 256;
            const int r = i >> 3, c = i & 7;
            const uint4* src = srcs[tile] + (size_t)r * 128 + kq + c;
            uint32_t dst = bufAddr + tile * TILE_BYTES + SWZ128(r * 128 + c * 16);
            CP_ASYNC16(dst, src);
        }
        CP_COMMIT();
    };

    float acc[4][4][4];
#pragma unroll
    for (int mt = 0; mt < 4; mt++)
#pragma unroll
        for (int nt = 0; nt < 4; nt++)
#pragma unroll
            for (int r = 0; r < 4; r++) acc[mt][nt][r] = 0.f;

    load_chunk(0, 0);
    CP_WAIT0();
    __syncthreads();

    const int aRow = wm * 64 + (lid & 15);
    const int aColH = (lid >> 4) * 16;
    const int bRow = wn * 32 + (lid & 7);
    const int bColH = ((lid >> 3) & 1) * 16;

#pragma unroll 1
    for (int ch = 0; ch < 16; ch++) {
        const int cur = ch & 1;
        if (ch < 15) load_chunk(ch + 1, cur ^ 1);

        const uint32_t bufAddr = sbase + cur * BUF_BYTES;
        const uint32_t aH = bufAddr;
        const uint32_t aL = bufAddr + TILE_BYTES;
        const uint32_t bH = bufAddr + 2 * TILE_BYTES;
        const uint32_t bL = bufAddr + 3 * TILE_BYTES;

#pragma unroll
        for (int ks = 0; ks < 4; ks++) {
            const int kByte = ks * 32;
            uint32_t ah[4][4], al[4][4], bh[4][2], bl[4][2];
#pragma unroll
            for (int mt = 0; mt < 4; mt++) {
                uint32_t off = SWZ128((aRow + mt * 16) * 128 + kByte + aColH);
                ldsm_x4(ah[mt], aH + off);
                ldsm_x4(al[mt], aL + off);
            }
#pragma unroll
            for (int nt = 0; nt < 4; nt++) {
                uint32_t off = SWZ128((bRow + nt * 8) * 128 + kByte + bColH);
                ldsm_x2(bh[nt], bH + off);
                ldsm_x2(bl[nt], bL + off);
            }
#pragma unroll
            for (int mt = 0; mt < 4; mt++)
#pragma unroll
                for (int nt = 0; nt < 4; nt++) {
                    mma16816(acc[mt][nt], ah[mt], bh[nt]);
                    mma16816(acc[mt][nt], ah[mt], bl[nt]);
                    mma16816(acc[mt][nt], al[mt], bh[nt]);
                }
        }

        if (ch < 15) CP_WAIT0();
        __syncthreads();
    }

    // Epilogue
    const int erow = mBase + wm * 64 + (lid >> 2);
    const int ecolBase = nBase + wn * 32 + 2 * (lid & 3);
#pragma unroll
    for (int nt = 0; nt < 4; nt++) {
        const int col = ecolBase + nt * 8;
        const float b0 = __ldg(bias + col), b1 = __ldg(bias + col + 1);
#pragma unroll
        for (int mt = 0; mt < 4; mt++) {
            const int r0 = erow + mt * 16;
            float v0 = (acc[mt][nt][0] + b0) * scale;
            float v1 = (acc[mt][nt][1] + b1) * scale;
            float v2 = (acc[mt][nt][2] + b0) * scale;
            float v3 = (acc[mt][nt][3] + b1) * scale;
            if (C) {
                *reinterpret_cast<float2*>(C + (size_t)r0 * DD + col)       = make_float2(v0, v1);
                *reinterpret_cast<float2*>(C + (size_t)(r0 + 8) * DD + col) = make_float2(v2, v3);
            } else {
                __nv_bfloat162 h0 = __floats2bfloat162_rn(v0, v1);
                __nv_bfloat162 h1 = __floats2bfloat162_rn(v2, v3);
                *reinterpret_cast<__nv_bfloat162*>(Ch + (size_t)r0 * DD + col)       = h0;
                *reinterpret_cast<__nv_bfloat162*>(Ch + (size_t)(r0 + 8) * DD + col) = h1;
                *reinterpret_cast<__nv_bfloat162*>(Cl + (size_t)r0 * DD + col) =
                    __floats2bfloat162_rn(v0 - __low2float(h0), v1 - __high2float(h0));
                *reinterpret_cast<__nv_bfloat162*>(Cl + (size_t)(r0 + 8) * DD + col) =
                    __floats2bfloat162_rn(v2 - __low2float(h1), v3 - __high2float(h1));
            }
        }
    }
}

// ---------------------------------------------------------------------------
// MMA flash attention. Q pre-scaled by 1/8. All operands bf16 hi/lo in
// [B,S,D] layout (head h = cols h*64..+63). Output -> (Oh,Ol) bf16 hi/lo.
// CTA: 128 query rows x one (b,h); 8 warps x 16 rows; BK=32 keys/iter.
// scores = Qh*Kh + Qh*Kl + Ql*Kh ; PV = Ph*Vh + Ph*Vl + Pl*Vh (fp32 acc).
// P A-fragments come directly from score accumulators (layout identity).
// ---------------------------------------------------------------------------
#define KV_BYTES 16384                 // Kh,Kl,Vh,Vl 32x128B each
#define ATT_SMEM (32768 + 2*KV_BYTES + 1024)

__global__ __launch_bounds__(256, 2) void attn_mma_kernel(
    const __nv_bfloat16* __restrict__ Qh, const __nv_bfloat16* __restrict__ Ql,
    const __nv_bfloat16* __restrict__ Kh, const __nv_bfloat16* __restrict__ Kl,
    const __nv_bfloat16* __restrict__ Vh, const __nv_bfloat16* __restrict__ Vl,
    __nv_bfloat16* __restrict__ Oh, __nv_bfloat16* __restrict__ Ol)
{
    extern __shared__ char smem[];
    const uint32_t sb = (smem_u32(smem) + 1023u) & ~1023u;
    const int tid = threadIdx.x;
    const int wid = tid >> 5;
    const int lid = tid & 31;
    const int bh  = blockIdx.y;
    const int b   = bh >> 4, h = bh & 15;
    const int qBase = blockIdx.x * 128;

    const uint32_t QH_OFF = 0, QL_OFF = 16384, KV_OFF = 32768;
    const size_t qOrg = (size_t)(b * SS + qBase) * DD + h * DKK;   // Q tile origin (elems)
    const size_t kOrg = (size_t)(b * SS) * DD + h * DKK;           // K/V batch origin

    // ---- stage Q (hi/lo) : 2 x 128 rows x 8 chunks of 16B ----
    {
        const int idx = tid & 1023;        // placeholder to keep pattern clear
        (void)idx;
#pragma unroll
        for (int j = 0; j < 8; j++) {
            int i  = tid + j * 256;        // 0..2047
            int sp = i >> 10;              // 0=hi 1=lo
            int r  = (i & 1023) >> 3;
            int c  = i & 7;
            const __nv_bfloat16* src = (sp ? Ql : Qh) + qOrg + (size_t)r * DD + c * 8;
            uint32_t dst = sb + (sp ? QL_OFF : QH_OFF) + SWZ128(r * 128 + c * 16);
            CP_ASYNC16(dst, src);
        }
    }
    // ---- K/V tile loader: 32 keys x 64 dims, 4 tiles (Kh,Kl,Vh,Vl) ----
    const __nv_bfloat16* kvsrc[4] = { Kh, Kl, Vh, Vl };
    auto load_kv = [&](int t, int buf) {
        const int r = tid >> 3, c = tid & 7;             // r 0..31, c 0..7
        const size_t g = kOrg + (size_t)(t * 32 + r) * DD + c * 8;
        const uint32_t dstb = sb + KV_OFF + buf * KV_BYTES + SWZ128(r * 128 + c * 16);
#pragma unroll
        for (int tile = 0; tile < 4; tile++)
            CP_ASYNC16(dstb + tile * 4096, kvsrc[tile] + g);
        CP_COMMIT();
    };

    load_kv(0, 0);
    CP_WAIT0();
    __syncthreads();

    // ---- Q fragments (held in regs for whole kernel) ----
    uint32_t qfh[4][4], qfl[4][4];
    {
        const int aRow = wid * 16 + (lid & 15);
        const int aColH = (lid >> 4) * 16;
#pragma unroll
        for (int ks = 0; ks < 4; ks++) {
            uint32_t off = SWZ128(aRow * 128 + ks * 32 + aColH);
            ldsm_x4(qfh[ks], sb + QH_OFF + off);
            ldsm_x4(qfl[ks], sb + QL_OFF + off);
        }
    }

    float o[8][4];
#pragma unroll
    for (int nt = 0; nt < 8; nt++)
#pragma unroll
        for (int r = 0; r < 4; r++) o[nt][r] = 0.f;
    float m0 = -1e30f, m1 = -1e30f, l0 = 0.f, l1 = 0.f;

    // fragment address components
    const uint32_t kFragBase = (lid & 7) * 128 + ((lid >> 3) & 1) * 16;       // + nt*1024 + ks*32
    const uint32_t vFragRow  = ((lid & 7) + 8 * ((lid >> 3) & 1)) * 128;      // + ks*2048 + nt*16

#pragma unroll 1
    for (int t = 0; t < SS / 32; t++) {
        const int cur = t & 1;
        if (t < SS / 32 - 1) load_kv(t + 1, cur ^ 1);

        const uint32_t kb = sb + KV_OFF + cur * KV_BYTES;

        // ---- scores: m16 x n32 x k64, bf16x3 ----
        float s[4][4];
#pragma unroll
        for (int nt = 0; nt < 4; nt++)
#pragma unroll
            for (int r = 0; r < 4; r++) s[nt][r] = 0.f;
#pragma unroll
        for (int ks = 0; ks < 4; ks++) {
#pragma unroll
            for (int nt = 0; nt < 4; nt++) {
                uint32_t kbh[2], kbl[2];
                uint32_t off = SWZ128(nt * 1024 + kFragBase + ks * 32);
                ldsm_x2(kbh, kb + off);            // Kh tile @ +0
                ldsm_x2(kbl, kb + 4096 + off);     // Kl tile
                mma16816(s[nt], qfh[ks], kbh);
                mma16816(s[nt], qfh[ks], kbl);
                mma16816(s[nt], qfl[ks], kbh);
            }
        }

        // ---- online softmax (rows r=lid>>2 and r+8; cols across lanes lid&3) ----
        float t0 = -1e30f, t1 = -1e30f;
#pragma unroll
        for (int nt = 0; nt < 4; nt++) {
            t0 = fmaxf(t0, fmaxf(s[nt][0], s[nt][1]));
            t1 = fmaxf(t1, fmaxf(s[nt][2], s[nt][3]));
        }
        t0 = fmaxf(t0, __shfl_xor_sync(0xffffffffu, t0, 1));
        t0 = fmaxf(t0, __shfl_xor_sync(0xffffffffu, t0, 2));
        t1 = fmaxf(t1, __shfl_xor_sync(0xffffffffu, t1, 1));
        t1 = fmaxf(t1, __shfl_xor_sync(0xffffffffu, t1, 2));
        const float mn0 = fmaxf(m0, t0), mn1 = fmaxf(m1, t1);
        const float c0 = __expf(m0 - mn0), c1 = __expf(m1 - mn1);
        m0 = mn0; m1 = mn1;

        uint32_t aPh[2][4], aPl[2][4];
        float rs0 = 0.f, rs1 = 0.f;
#pragma unroll
        for (int nt = 0; nt < 4; nt++) {
            float p0 = __expf(s[nt][0] - m0);
            float p1 = __expf(s[nt][1] - m0);
            float p2 = __expf(s[nt][2] - m1);
            float p3 = __expf(s[nt][3] - m1);
            rs0 += p0 + p1; rs1 += p2 + p3;
            const int ks = nt >> 1, pos = (nt & 1) * 2;
            __nv_bfloat162 hA = __floats2bfloat162_rn(p0, p1);
            __nv_bfloat162 hB = __floats2bfloat162_rn(p2, p3);
            aPh[ks][pos]     = *reinterpret_cast<uint32_t*>(&hA);
            aPh[ks][pos + 1] = *reinterpret_cast<uint32_t*>(&hB);
            aPl[ks][pos]     = packbf2(p0 - __low2float(hA), p1 - __high2float(hA));
            aPl[ks][pos + 1] = packbf2(p2 - __low2float(hB), p3 - __high2float(hB));
        }
        rs0 += __shfl_xor_sync(0xffffffffu, rs0, 1);
        rs0 += __shfl_xor_sync(0xffffffffu, rs0, 2);
        rs1 += __shfl_xor_sync(0xffffffffu, rs1, 1);
        rs1 += __shfl_xor_sync(0xffffffffu, rs1, 2);
        l0 = l0 * c0 + rs0;
        l1 = l1 * c1 + rs1;

#pragma unroll
        for (int nt = 0; nt < 8; nt++) {
            o[nt][0] *= c0; o[nt][1] *= c0;
            o[nt][2] *= c1; o[nt][3] *= c1;
        }

        // ---- PV: m16 x n64 x k32, bf16x3 (V via ldmatrix.trans) ----
#pragma unroll
        for (int ks = 0; ks < 2; ks++) {
#pragma unroll
            for (int nt = 0; nt < 8; nt++) {
                uint32_t vbh[2], vbl[2];
                uint32_t off = SWZ128(ks * 2048 + vFragRow + nt * 16);
                ldsm_x2t(vbh, kb + 8192 + off);     // Vh tile
                ldsm_x2t(vbl, kb + 12288 + off);    // Vl tile
                mma16816(o[nt], aPh[ks], vbh);
                mma16816(o[nt], aPh[ks], vbl);
                mma16816(o[nt], aPl[ks], vbh);
            }
        }

        CP_WAIT0();
        __syncthreads();
    }

    // ---- epilogue: normalize, split to bf16 hi/lo, write [B,S,D] ----
    const float i0 = 1.f / l0, i1 = 1.f / l1;
    const size_t row0 = (size_t)(b * SS + qBase + wid * 16 + (lid >> 2));
    const int colBase = h * DKK + 2 * (lid & 3);
#pragma unroll
    for (int nt = 0; nt < 8; nt++) {
        const int col = colBase + nt * 8;
        float v0 = o[nt][0] * i0, v1 = o[nt][1] * i0;
        float v2 = o[nt][2] * i1, v3 = o[nt][3] * i1;
        __nv_bfloat162 h0 = __floats2bfloat162_rn(v0, v1);
        __nv_bfloat162 h1 = __floats2bfloat162_rn(v2, v3);
        *reinterpret_cast<__nv_bfloat162*>(Oh + row0 * DD + col)       = h0;
        *reinterpret_cast<__nv_bfloat162*>(Oh + (row0 + 8) * DD + col) = h1;
        *reinterpret_cast<__nv_bfloat162*>(Ol + row0 * DD + col) =
            __floats2bfloat162_rn(v0 - __low2float(h0), v1 - __high2float(h0));
        *reinterpret_cast<__nv_bfloat162*>(Ol + (row0 + 8) * DD + col) =
            __floats2bfloat162_rn(v2 - __low2float(h1), v3 - __high2float(h1));
    }
}

// ---------------------------------------------------------------------------
// kernel_launch
// ---------------------------------------------------------------------------
extern "C" void kernel_launch(void* const* d_in, const int* in_sizes, int n_in,
                              void* d_out, int out_size)
{
    const float* query = (const float*)d_in[0];
    const float* key   = (const float*)d_in[1];
    const float* value = (const float*)d_in[2];
    const float* Wq    = (const float*)d_in[3];
    const float* bq    = (const float*)d_in[4];
    const float* Wk    = (const float*)d_in[5];
    const float* bk    = (const float*)d_in[6];
    const float* Wv    = (const float*)d_in[7];
    const float* bv    = (const float*)d_in[8];
    const float* Wo    = (const float*)d_in[9];
    const float* bo    = (const float*)d_in[10];
    float* out = (float*)d_out;

    __nv_bfloat16 *qh, *ql, *kh, *kl, *vh, *vl, *ah, *al, *wh, *wl;
    cudaGetSymbolAddress((void**)&qh, g_qh);
    cudaGetSymbolAddress((void**)&ql, g_ql);
    cudaGetSymbolAddress((void**)&kh, g_kh);
    cudaGetSymbolAddress((void**)&kl, g_kl);
    cudaGetSymbolAddress((void**)&vh, g_vh);
    cudaGetSymbolAddress((void**)&vl, g_vl);
    cudaGetSymbolAddress((void**)&ah, g_ah);
    cudaGetSymbolAddress((void**)&al, g_al);
    cudaGetSymbolAddress((void**)&wh, g_wh);
    cudaGetSymbolAddress((void**)&wl, g_wl);

    cudaFuncSetAttribute(gemm_tc_kernel,
                         cudaFuncAttributeMaxDynamicSharedMemorySize, GEMM_SMEM);
    cudaFuncSetAttribute(attn_mma_kernel,
                         cudaFuncAttributeMaxDynamicSharedMemorySize, ATT_SMEM);

    const int n4a = MROWS * DD / 4;
    const int n4w = DD * DD / 4;
    dim3 gGrid(DD / 128, MROWS / 128);   // (8, 64)

    // Q projection (scores scale 1/8 folded into Q)
    split_kernel<<<n4a / 256, 256>>>(query, ah, al, n4a);
    split_kernel<<<n4w / 256, 256>>>(Wq, wh, wl, n4w);
    gemm_tc_kernel<<<gGrid, 256, GEMM_SMEM>>>(ah, al, wh, wl, bq, nullptr, qh, ql, 0.125f);
    // K projection
    split_kernel<<<n4a / 256, 256>>>(key, ah, al, n4a);
    split_kernel<<<n4w / 256, 256>>>(Wk, wh, wl, n4w);
    gemm_tc_kernel<<<gGrid, 256, GEMM_SMEM>>>(ah, al, wh, wl, bk, nullptr, kh, kl, 1.0f);
    // V projection
    split_kernel<<<n4a / 256, 256>>>(value, ah, al, n4a);
    split_kernel<<<n4w / 256, 256>>>(Wv, wh, wl, n4w);
    gemm_tc_kernel<<<gGrid, 256, GEMM_SMEM>>>(ah, al, wh, wl, bv, nullptr, vh, vl, 1.0f);

    // Attention -> (ah, al) bf16 hi/lo
    dim3 aGrid(SS / 128, BB * HH);       // (16, 64)
    attn_mma_kernel<<<aGrid, 256, ATT_SMEM>>>(qh, ql, kh, kl, vh, vl, ah, al);

    // Output projection -> fp32 d_out
    split_kernel<<<n4w / 256, 256>>>(Wo, wh, wl, n4w);
    gemm_tc_kernel<<<gGrid, 256, GEMM_SMEM>>>(ah, al, wh, wl, bo, out, nullptr, nullptr, 1.0f);
}

// round 14
// speedup vs baseline: 1.5322x; 1.0026x over previous
#include <cuda_runtime.h>
#include <cuda_bf16.h>
#include <cstdint>

// Problem constants
#define BB 4
#define SS 2048
#define DD 1024
#define HH 16
#define DKK 64
#define MROWS (BB*SS)          // 8192

// ---------------------------------------------------------------------------
// Scratch (device globals — no allocations allowed)
// ---------------------------------------------------------------------------
__device__ __nv_bfloat16 g_qh[MROWS*DD], g_ql[MROWS*DD];   // Q proj out (pre-scaled 1/8)
__device__ __nv_bfloat16 g_kh[MROWS*DD], g_kl[MROWS*DD];   // K proj out
__device__ __nv_bfloat16 g_vh[MROWS*DD], g_vl[MROWS*DD];   // V proj out
__device__ __nv_bfloat16 g_ah[MROWS*DD], g_al[MROWS*DD];   // GEMM-A splits / attn out
__device__ __nv_bfloat16 g_wh[DD*DD],   g_wl[DD*DD];       // weight splits

// ---------------------------------------------------------------------------
// Helpers
// ---------------------------------------------------------------------------
__device__ __forceinline__ uint32_t smem_u32(const void* p) {
    uint32_t a;
    asm("{ .reg .u64 t; cvta.to.shared.u64 t, %1; cvt.u32.u64 %0, t; }" : "=r"(a) : "l"(p));
    return a;
}
#define SWZ128(o) ((o) ^ (((o) >> 3) & 0x70))

#define CP_ASYNC16(dst, src) \
    asm volatile("cp.async.cg.shared.global [%0], [%1], 16;" :: "r"(dst), "l"(src))
#define CP_COMMIT()  asm volatile("cp.async.commit_group;" ::: "memory")
#define CP_WAIT0()   asm volatile("cp.async.wait_group 0;" ::: "memory")

__device__ __forceinline__ void ldsm_x4(uint32_t* r, uint32_t addr) {
    asm volatile("ldmatrix.sync.aligned.m8n8.x4.shared.b16 {%0,%1,%2,%3}, [%4];"
        : "=r"(r[0]), "=r"(r[1]), "=r"(r[2]), "=r"(r[3]) : "r"(addr));
}
__device__ __forceinline__ void ldsm_x2(uint32_t* r, uint32_t addr) {
    asm volatile("ldmatrix.sync.aligned.m8n8.x2.shared.b16 {%0,%1}, [%2];"
        : "=r"(r[0]), "=r"(r[1]) : "r"(addr));
}
__device__ __forceinline__ void ldsm_x2t(uint32_t* r, uint32_t addr) {
    asm volatile("ldmatrix.sync.aligned.m8n8.x2.trans.shared.b16 {%0,%1}, [%2];"
        : "=r"(r[0]), "=r"(r[1]) : "r"(addr));
}
__device__ __forceinline__ void mma16816(float* d, const uint32_t* a, const uint32_t* b) {
    asm volatile("mma.sync.aligned.m16n8k16.row.col.f32.bf16.bf16.f32 "
        "{%0,%1,%2,%3}, {%4,%5,%6,%7}, {%8,%9}, {%0,%1,%2,%3};"
        : "+f"(d[0]), "+f"(d[1]), "+f"(d[2]), "+f"(d[3])
        : "r"(a[0]), "r"(a[1]), "r"(a[2]), "r"(a[3]), "r"(b[0]), "r"(b[1]));
}
__device__ __forceinline__ uint32_t packbf2(float x, float y) {
    __nv_bfloat162 t = __floats2bfloat162_rn(x, y);
    return *reinterpret_cast<uint32_t*>(&t);
}

// ---------------------------------------------------------------------------
// Split fp32 -> (bf16 hi, bf16 lo) with residual capture
// ---------------------------------------------------------------------------
__global__ __launch_bounds__(256) void split_kernel(
    const float* __restrict__ x, __nv_bfloat16* __restrict__ hi,
    __nv_bfloat16* __restrict__ lo, int n4)
{
    int i = blockIdx.x * 256 + threadIdx.x;
    if (i >= n4) return;
    float4 v = reinterpret_cast<const float4*>(x)[i];
    __nv_bfloat162 h0 = __floats2bfloat162_rn(v.x, v.y);
    __nv_bfloat162 h1 = __floats2bfloat162_rn(v.z, v.w);
    float r0 = v.x - __low2float(h0), r1 = v.y - __high2float(h0);
    float r2 = v.z - __low2float(h1), r3 = v.w - __high2float(h1);
    __nv_bfloat162* hp = reinterpret_cast<__nv_bfloat162*>(hi);
    __nv_bfloat162* lp = reinterpret_cast<__nv_bfloat162*>(lo);
    hp[2*i]   = h0;
    hp[2*i+1] = h1;
    lp[2*i]   = __floats2bfloat162_rn(r0, r1);
    lp[2*i+1] = __floats2bfloat162_rn(r2, r3);
}

// ---------------------------------------------------------------------------
// HMMA bf16x3 GEMM (NT): acc = sum_k A[i,k]*W[j,k]; out = (acc + bias[j])*scale
// Output either fp32 C, or bf16 hi/lo pair (Ch,Cl).
// CTA tile 128x128, K chunk 64, SW128 smem, cp.async double-buffered.
// 8 warps in 2(m) x 4(n); warp tile 64x32 via m16n8k16.
// ---------------------------------------------------------------------------
#define TILE_BYTES 16384               // 128 rows x 128B
#define BUF_BYTES  (4*TILE_BYTES)      // Ah,Al,Bh,Bl
#define GEMM_SMEM  (1024 + 2*BUF_BYTES)

__global__ __launch_bounds__(256, 1) void gemm_tc_kernel(
    const __nv_bfloat16* __restrict__ Ah, const __nv_bfloat16* __restrict__ Al,
    const __nv_bfloat16* __restrict__ Bh, const __nv_bfloat16* __restrict__ Bl,
    const float* __restrict__ bias, float* __restrict__ C,
    __nv_bfloat16* __restrict__ Ch, __nv_bfloat16* __restrict__ Cl, float scale)
{
    extern __shared__ char smem[];
    const uint32_t sbase = (smem_u32(smem) + 1023u) & ~1023u;
    const int tid = threadIdx.x;
    const int wid = tid >> 5;
    const int lid = tid & 31;
    const int wm  = wid >> 2;          // 0..1
    const int wn  = wid & 3;           // 0..3
    const int nBase = blockIdx.x * 128;
    const int mBase = blockIdx.y * 128;

    const uint4* srcs[4] = {
        reinterpret_cast<const uint4*>(Ah) + (size_t)mBase * 128,
        reinterpret_cast<const uint4*>(Al) + (size_t)mBase * 128,
        reinterpret_cast<const uint4*>(Bh) + (size_t)nBase * 128,
        reinterpret_cast<const uint4*>(Bl) + (size_t)nBase * 128
    };

    auto load_chunk = [&](int ch, int buf) {
        const int kq = ch * 8;
        const uint32_t bufAddr = sbase + buf * BUF_BYTES;
#pragma unroll
        for (int t = 0; t < 16; t++) {
            const int tile = t >> 2;
            const int i = tid + (t & 3) * 256;
            const int r = i >> 3, c = i & 7;
            const uint4* src = srcs[tile] + (size_t)r * 128 + kq + c;
            uint32_t dst = bufAddr + tile * TILE_BYTES + SWZ128(r * 128 + c * 16);
            CP_ASYNC16(dst, src);
        }
        CP_COMMIT();
    };

    float acc[4][4][4];
#pragma unroll
    for (int mt = 0; mt < 4; mt++)
#pragma unroll
        for (int nt = 0; nt < 4; nt++)
#pragma unroll
            for (int r = 0; r < 4; r++) acc[mt][nt][r] = 0.f;

    load_chunk(0, 0);
    CP_WAIT0();
    __syncthreads();

    const int aRow = wm * 64 + (lid & 15);
    const int aColH = (lid >> 4) * 16;
    const int bRow = wn * 32 + (lid & 7);
    const int bColH = ((lid >> 3) & 1) * 16;

#pragma unroll 1
    for (int ch = 0; ch < 16; ch++) {
        const int cur = ch & 1;
        if (ch < 15) load_chunk(ch + 1, cur ^ 1);

        const uint32_t bufAddr = sbase + cur * BUF_BYTES;
        const uint32_t aH = bufAddr;
        const uint32_t aL = bufAddr + TILE_BYTES;
        const uint32_t bH = bufAddr + 2 * TILE_BYTES;
        const uint32_t bL = bufAddr + 3 * TILE_BYTES;

#pragma unroll
        for (int ks = 0; ks < 4; ks++) {
            const int kByte = ks * 32;
            uint32_t ah[4][4], al[4][4], bh[4][2], bl[4][2];
#pragma unroll
            for (int mt = 0; mt < 4; mt++) {
                uint32_t off = SWZ128((aRow + mt * 16) * 128 + kByte + aColH);
                ldsm_x4(ah[mt], aH + off);
                ldsm_x4(al[mt], aL + off);
            }
#pragma unroll
            for (int nt = 0; nt < 4; nt++) {
                uint32_t off = SWZ128((bRow + nt * 8) * 128 + kByte + bColH);
                ldsm_x2(bh[nt], bH + off);
                ldsm_x2(bl[nt], bL + off);
            }
#pragma unroll
            for (int mt = 0; mt < 4; mt++)
#pragma unroll
                for (int nt = 0; nt < 4; nt++) {
                    mma16816(acc[mt][nt], ah[mt], bh[nt]);
                    mma16816(acc[mt][nt], ah[mt], bl[nt]);
                    mma16816(acc[mt][nt], al[mt], bh[nt]);
                }
        }

        if (ch < 15) CP_WAIT0();
        __syncthreads();
    }

    // Epilogue
    const int erow = mBase + wm * 64 + (lid >> 2);
    const int ecolBase = nBase + wn * 32 + 2 * (lid & 3);
#pragma unroll
    for (int nt = 0; nt < 4; nt++) {
        const int col = ecolBase + nt * 8;
        const float b0 = __ldg(bias + col), b1 = __ldg(bias + col + 1);
#pragma unroll
        for (int mt = 0; mt < 4; mt++) {
            const int r0 = erow + mt * 16;
            float v0 = (acc[mt][nt][0] + b0) * scale;
            float v1 = (acc[mt][nt][1] + b1) * scale;
            float v2 = (acc[mt][nt][2] + b0) * scale;
            float v3 = (acc[mt][nt][3] + b1) * scale;
            if (C) {
                *reinterpret_cast<float2*>(C + (size_t)r0 * DD + col)       = make_float2(v0, v1);
                *reinterpret_cast<float2*>(C + (size_t)(r0 + 8) * DD + col) = make_float2(v2, v3);
            } else {
                __nv_bfloat162 h0 = __floats2bfloat162_rn(v0, v1);
                __nv_bfloat162 h1 = __floats2bfloat162_rn(v2, v3);
                *reinterpret_cast<__nv_bfloat162*>(Ch + (size_t)r0 * DD + col)       = h0;
                *reinterpret_cast<__nv_bfloat162*>(Ch + (size_t)(r0 + 8) * DD + col) = h1;
                *reinterpret_cast<__nv_bfloat162*>(Cl + (size_t)r0 * DD + col) =
                    __floats2bfloat162_rn(v0 - __low2float(h0), v1 - __high2float(h0));
                *reinterpret_cast<__nv_bfloat162*>(Cl + (size_t)(r0 + 8) * DD + col) =
                    __floats2bfloat162_rn(v2 - __low2float(h1), v3 - __high2float(h1));
            }
        }
    }
}

// ---------------------------------------------------------------------------
// MMA flash attention. Q pre-scaled by 1/8. All operands bf16 hi/lo in
// [B,S,D] layout (head h = cols h*64..+63). Output -> (Oh,Ol) bf16 hi/lo.
// CTA: 128 query rows x one (b,h); 8 warps x 16 rows; BK=32 keys/iter.
// scores = Qh*Kh + Qh*Kl + Ql*Kh ; PV = Ph*Vh + Ph*Vl + Pl*Vh (fp32 acc).
// P A-fragments come directly from score accumulators (layout identity).
// ---------------------------------------------------------------------------
#define KV_BYTES 16384                 // Kh,Kl,Vh,Vl 32x128B each
#define ATT_SMEM (32768 + 2*KV_BYTES + 1024)

__global__ __launch_bounds__(256, 2) void attn_mma_kernel(
    const __nv_bfloat16* __restrict__ Qh, const __nv_bfloat16* __restrict__ Ql,
    const __nv_bfloat16* __restrict__ Kh, const __nv_bfloat16* __restrict__ Kl,
    const __nv_bfloat16* __restrict__ Vh, const __nv_bfloat16* __restrict__ Vl,
    __nv_bfloat16* __restrict__ Oh, __nv_bfloat16* __restrict__ Ol)
{
    extern __shared__ char smem[];
    const uint32_t sb = (smem_u32(smem) + 1023u) & ~1023u;
    const int tid = threadIdx.x;
    const int wid = tid >> 5;
    const int lid = tid & 31;
    const int bh  = blockIdx.y;
    const int b   = bh >> 4, h = bh & 15;
    const int qBase = blockIdx.x * 128;

    const uint32_t QH_OFF = 0, QL_OFF = 16384, KV_OFF = 32768;
    const size_t qOrg = (size_t)(b * SS + qBase) * DD + h * DKK;   // Q tile origin (elems)
    const size_t kOrg = (size_t)(b * SS) * DD + h * DKK;           // K/V batch origin

    // ---- stage Q (hi/lo) : 2 x 128 rows x 8 chunks of 16B ----
    {
        const int idx = tid & 1023;        // placeholder to keep pattern clear
        (void)idx;
#pragma unroll
        for (int j = 0; j < 8; j++) {
            int i  = tid + j * 256;        // 0..2047
            int sp = i >> 10;              // 0=hi 1=lo
            int r  = (i & 1023) >> 3;
            int c  = i & 7;
            const __nv_bfloat16* src = (sp ? Ql : Qh) + qOrg + (size_t)r * DD + c * 8;
            uint32_t dst = sb + (sp ? QL_OFF : QH_OFF) + SWZ128(r * 128 + c * 16);
            CP_ASYNC16(dst, src);
        }
    }
    // ---- K/V tile loader: 32 keys x 64 dims, 4 tiles (Kh,Kl,Vh,Vl) ----
    const __nv_bfloat16* kvsrc[4] = { Kh, Kl, Vh, Vl };
    auto load_kv = [&](int t, int buf) {
        const int r = tid >> 3, c = tid & 7;             // r 0..31, c 0..7
        const size_t g = kOrg + (size_t)(t * 32 + r) * DD + c * 8;
        const uint32_t dstb = sb + KV_OFF + buf * KV_BYTES + SWZ128(r * 128 + c * 16);
#pragma unroll
        for (int tile = 0; tile < 4; tile++)
            CP_ASYNC16(dstb + tile * 4096, kvsrc[tile] + g);
        CP_COMMIT();
    };

    load_kv(0, 0);
    CP_WAIT0();
    __syncthreads();

    // ---- Q fragments (held in regs for whole kernel) ----
    uint32_t qfh[4][4], qfl[4][4];
    {
        const int aRow = wid * 16 + (lid & 15);
        const int aColH = (lid >> 4) * 16;
#pragma unroll
        for (int ks = 0; ks < 4; ks++) {
            uint32_t off = SWZ128(aRow * 128 + ks * 32 + aColH);
            ldsm_x4(qfh[ks], sb + QH_OFF + off);
            ldsm_x4(qfl[ks], sb + QL_OFF + off);
        }
    }

    float o[8][4];
#pragma unroll
    for (int nt = 0; nt < 8; nt++)
#pragma unroll
        for (int r = 0; r < 4; r++) o[nt][r] = 0.f;
    float m0 = -1e30f, m1 = -1e30f, l0 = 0.f, l1 = 0.f;

    // fragment address components
    const uint32_t kFragBase = (lid & 7) * 128 + ((lid >> 3) & 1) * 16;       // + nt*1024 + ks*32
    const uint32_t vFragRow  = ((lid & 7) + 8 * ((lid >> 3) & 1)) * 128;      // + ks*2048 + nt*16

#pragma unroll 1
    for (int t = 0; t < SS / 32; t++) {
        const int cur = t & 1;
        if (t < SS / 32 - 1) load_kv(t + 1, cur ^ 1);

        const uint32_t kb = sb + KV_OFF + cur * KV_BYTES;

        // ---- scores: m16 x n32 x k64, bf16x3 ----
        float s[4][4];
#pragma unroll
        for (int nt = 0; nt < 4; nt++)
#pragma unroll
            for (int r = 0; r < 4; r++) s[nt][r] = 0.f;
#pragma unroll
        for (int ks = 0; ks < 4; ks++) {
#pragma unroll
            for (int nt = 0; nt < 4; nt++) {
                uint32_t kbh[2], kbl[2];
                uint32_t off = SWZ128(nt * 1024 + kFragBase + ks * 32);
                ldsm_x2(kbh, kb + off);            // Kh tile @ +0
                ldsm_x2(kbl, kb + 4096 + off);     // Kl tile
                mma16816(s[nt], qfh[ks], kbh);
                mma16816(s[nt], qfh[ks], kbl);
                mma16816(s[nt], qfl[ks], kbh);
            }
        }

        // ---- online softmax (rows r=lid>>2 and r+8; cols across lanes lid&3) ----
        float t0 = -1e30f, t1 = -1e30f;
#pragma unroll
        for (int nt = 0; nt < 4; nt++) {
            t0 = fmaxf(t0, fmaxf(s[nt][0], s[nt][1]));
            t1 = fmaxf(t1, fmaxf(s[nt][2], s[nt][3]));
        }
        t0 = fmaxf(t0, __shfl_xor_sync(0xffffffffu, t0, 1));
        t0 = fmaxf(t0, __shfl_xor_sync(0xffffffffu, t0, 2));
        t1 = fmaxf(t1, __shfl_xor_sync(0xffffffffu, t1, 1));
        t1 = fmaxf(t1, __shfl_xor_sync(0xffffffffu, t1, 2));
        const float mn0 = fmaxf(m0, t0), mn1 = fmaxf(m1, t1);
        const float c0 = __expf(m0 - mn0), c1 = __expf(m1 - mn1);
        m0 = mn0; m1 = mn1;

        uint32_t aPh[2][4], aPl[2][4];
        float rs0 = 0.f, rs1 = 0.f;
#pragma unroll
        for (int nt = 0; nt < 4; nt++) {
            float p0 = __expf(s[nt][0] - m0);
            float p1 = __expf(s[nt][1] - m0);
            float p2 = __expf(s[nt][2] - m1);
            float p3 = __expf(s[nt][3] - m1);
            rs0 += p0 + p1; rs1 += p2 + p3;
            const int ks = nt >> 1, pos = (nt & 1) * 2;
            __nv_bfloat162 hA = __floats2bfloat162_rn(p0, p1);
            __nv_bfloat162 hB = __floats2bfloat162_rn(p2, p3);
            aPh[ks][pos]     = *reinterpret_cast<uint32_t*>(&hA);
            aPh[ks][pos + 1] = *reinterpret_cast<uint32_t*>(&hB);
            aPl[ks][pos]     = packbf2(p0 - __low2float(hA), p1 - __high2float(hA));
            aPl[ks][pos + 1] = packbf2(p2 - __low2float(hB), p3 - __high2float(hB));
        }
        rs0 += __shfl_xor_sync(0xffffffffu, rs0, 1);
        rs0 += __shfl_xor_sync(0xffffffffu, rs0, 2);
        rs1 += __shfl_xor_sync(0xffffffffu, rs1, 1);
        rs1 += __shfl_xor_sync(0xffffffffu, rs1, 2);
        l0 = l0 * c0 + rs0;
        l1 = l1 * c1 + rs1;

#pragma unroll
        for (int nt = 0; nt < 8; nt++) {
            o[nt][0] *= c0; o[nt][1] *= c0;
            o[nt][2] *= c1; o[nt][3] *= c1;
        }

        // ---- PV: m16 x n64 x k32, bf16x3 (V via ldmatrix.trans) ----
#pragma unroll
        for (int ks = 0; ks < 2; ks++) {
#pragma unroll
            for (int nt = 0; nt < 8; nt++) {
                uint32_t vbh[2], vbl[2];
                uint32_t off = SWZ128(ks * 2048 + vFragRow + nt * 16);
                ldsm_x2t(vbh, kb + 8192 + off);     // Vh tile
                ldsm_x2t(vbl, kb + 12288 + off);    // Vl tile
                mma16816(o[nt], aPh[ks], vbh);
                mma16816(o[nt], aPh[ks], vbl);
                mma16816(o[nt], aPl[ks], vbh);
            }
        }

        CP_WAIT0();
        __syncthreads();
    }

    // ---- epilogue: normalize, split to bf16 hi/lo, write [B,S,D] ----
    const float i0 = 1.f / l0, i1 = 1.f / l1;
    const size_t row0 = (size_t)(b * SS + qBase + wid * 16 + (lid >> 2));
    const int colBase = h * DKK + 2 * (lid & 3);
#pragma unroll
    for (int nt = 0; nt < 8; nt++) {
        const int col = colBase + nt * 8;
        float v0 = o[nt][0] * i0, v1 = o[nt][1] * i0;
        float v2 = o[nt][2] * i1, v3 = o[nt][3] * i1;
        __nv_bfloat162 h0 = __floats2bfloat162_rn(v0, v1);
        __nv_bfloat162 h1 = __floats2bfloat162_rn(v2, v3);
        *reinterpret_cast<__nv_bfloat162*>(Oh + row0 * DD + col)       = h0;
        *reinterpret_cast<__nv_bfloat162*>(Oh + (row0 + 8) * DD + col) = h1;
        *reinterpret_cast<__nv_bfloat162*>(Ol + row0 * DD + col) =
            __floats2bfloat162_rn(v0 - __low2float(h0), v1 - __high2float(h0));
        *reinterpret_cast<__nv_bfloat162*>(Ol + (row0 + 8) * DD + col) =
            __floats2bfloat162_rn(v2 - __low2float(h1), v3 - __high2float(h1));
    }
}

// ---------------------------------------------------------------------------
// kernel_launch
// ---------------------------------------------------------------------------
extern "C" void kernel_launch(void* const* d_in, const int* in_sizes, int n_in,
                              void* d_out, int out_size)
{
    const float* query = (const float*)d_in[0];
    const float* key   = (const float*)d_in[1];
    const float* value = (const float*)d_in[2];
    const float* Wq    = (const float*)d_in[3];
    const float* bq    = (const float*)d_in[4];
    const float* Wk    = (const float*)d_in[5];
    const float* bk    = (const float*)d_in[6];
    const float* Wv    = (const float*)d_in[7];
    const float* bv    = (const float*)d_in[8];
    const float* Wo    = (const float*)d_in[9];
    const float* bo    = (const float*)d_in[10];
    float* out = (float*)d_out;

    __nv_bfloat16 *qh, *ql, *kh, *kl, *vh, *vl, *ah, *al, *wh, *wl;
    cudaGetSymbolAddress((void**)&qh, g_qh);
    cudaGetSymbolAddress((void**)&ql, g_ql);
    cudaGetSymbolAddress((void**)&kh, g_kh);
    cudaGetSymbolAddress((void**)&kl, g_kl);
    cudaGetSymbolAddress((void**)&vh, g_vh);
    cudaGetSymbolAddress((void**)&vl, g_vl);
    cudaGetSymbolAddress((void**)&ah, g_ah);
    cudaGetSymbolAddress((void**)&al, g_al);
    cudaGetSymbolAddress((void**)&wh, g_wh);
    cudaGetSymbolAddress((void**)&wl, g_wl);

    cudaFuncSetAttribute(gemm_tc_kernel,
                         cudaFuncAttributeMaxDynamicSharedMemorySize, GEMM_SMEM);
    cudaFuncSetAttribute(attn_mma_kernel,
                         cudaFuncAttributeMaxDynamicSharedMemorySize, ATT_SMEM);

    const int n4a = MROWS * DD / 4;
    const int n4w = DD * DD / 4;
    dim3 gGrid(DD / 128, MROWS / 128);   // (8, 64)

    // Q projection (scores scale 1/8 folded into Q)
    split_kernel<<<n4a / 256, 256>>>(query, ah, al, n4a);
    split_kernel<<<n4w / 256, 256>>>(Wq, wh, wl, n4w);
    gemm_tc_kernel<<<gGrid, 256, GEMM_SMEM>>>(ah, al, wh, wl, bq, nullptr, qh, ql, 0.125f);
    // K projection
    split_kernel<<<n4a / 256, 256>>>(key, ah, al, n4a);
    split_kernel<<<n4w / 256, 256>>>(Wk, wh, wl, n4w);
    gemm_tc_kernel<<<gGrid, 256, GEMM_SMEM>>>(ah, al, wh, wl, bk, nullptr, kh, kl, 1.0f);
    // V projection
    split_kernel<<<n4a / 256, 256>>>(value, ah, al, n4a);
    split_kernel<<<n4w / 256, 256>>>(Wv, wh, wl, n4w);
    gemm_tc_kernel<<<gGrid, 256, GEMM_SMEM>>>(ah, al, wh, wl, bv, nullptr, vh, vl, 1.0f);

    // Attention -> (ah, al) bf16 hi/lo
    dim3 aGrid(SS / 128, BB * HH);       // (16, 64)
    attn_mma_kernel<<<aGrid, 256, ATT_SMEM>>>(qh, ql, kh, kl, vh, vl, ah, al);

    // Output projection -> fp32 d_out
    split_kernel<<<n4w / 256, 256>>>(Wo, wh, wl, n4w);
    gemm_tc_kernel<<<gGrid, 256, GEMM_SMEM>>>(ah, al, wh, wl, bo, out, nullptr, nullptr, 1.0f);
}

// round 15
// speedup vs baseline: 1.5811x; 1.0320x over previous
#include <cuda_runtime.h>
#include <cuda_bf16.h>
#include <cstdint>

// Problem constants
#define BB 4
#define SS 2048
#define DD 1024
#define HH 16
#define DKK 64
#define MROWS (BB*SS)          // 8192

// ---------------------------------------------------------------------------
// Scratch (device globals — no allocations allowed)
// ---------------------------------------------------------------------------
__device__ __nv_bfloat16 g_qh[MROWS*DD], g_ql[MROWS*DD];     // Q proj out (pre-scaled 1/8)
__device__ __nv_bfloat16 g_kh[MROWS*DD], g_kl[MROWS*DD];     // K proj out
__device__ __nv_bfloat16 g_vh[MROWS*DD], g_vl[MROWS*DD];     // V proj out
__device__ __nv_bfloat16 g_aqh[MROWS*DD], g_aql[MROWS*DD];   // activation splits
__device__ __nv_bfloat16 g_akh[MROWS*DD], g_akl[MROWS*DD];
__device__ __nv_bfloat16 g_avh[MROWS*DD], g_avl[MROWS*DD];
__device__ __nv_bfloat16 g_oh[MROWS*DD],  g_ol[MROWS*DD];    // attention out
__device__ __nv_bfloat16 g_wqh[DD*DD], g_wql[DD*DD];         // weight splits
__device__ __nv_bfloat16 g_wkh[DD*DD], g_wkl[DD*DD];
__device__ __nv_bfloat16 g_wvh[DD*DD], g_wvl[DD*DD];
__device__ __nv_bfloat16 g_woh[DD*DD], g_wol[DD*DD];

// ---------------------------------------------------------------------------
// Helpers
// ---------------------------------------------------------------------------
__device__ __forceinline__ uint32_t smem_u32(const void* p) {
    uint32_t a;
    asm("{ .reg .u64 t; cvta.to.shared.u64 t, %1; cvt.u32.u64 %0, t; }" : "=r"(a) : "l"(p));
    return a;
}
#define SWZ128(o) ((o) ^ (((o) >> 3) & 0x70))
#define SWZ64(o)  ((o) ^ (((o) >> 3) & 0x30))

#define CP_ASYNC16(dst, src) \
    asm volatile("cp.async.cg.shared.global [%0], [%1], 16;" :: "r"(dst), "l"(src))
#define CP_COMMIT()  asm volatile("cp.async.commit_group;" ::: "memory")
#define CP_WAIT0()   asm volatile("cp.async.wait_group 0;" ::: "memory")
#define CP_WAIT1()   asm volatile("cp.async.wait_group 1;" ::: "memory")

__device__ __forceinline__ void ldsm_x4(uint32_t* r, uint32_t addr) {
    asm volatile("ldmatrix.sync.aligned.m8n8.x4.shared.b16 {%0,%1,%2,%3}, [%4];"
        : "=r"(r[0]), "=r"(r[1]), "=r"(r[2]), "=r"(r[3]) : "r"(addr));
}
__device__ __forceinline__ void ldsm_x4t(uint32_t* r, uint32_t addr) {
    asm volatile("ldmatrix.sync.aligned.m8n8.x4.trans.shared.b16 {%0,%1,%2,%3}, [%4];"
        : "=r"(r[0]), "=r"(r[1]), "=r"(r[2]), "=r"(r[3]) : "r"(addr));
}
__device__ __forceinline__ void mma16816(float* d, const uint32_t* a, const uint32_t* b) {
    asm volatile("mma.sync.aligned.m16n8k16.row.col.f32.bf16.bf16.f32 "
        "{%0,%1,%2,%3}, {%4,%5,%6,%7}, {%8,%9}, {%0,%1,%2,%3};"
        : "+f"(d[0]), "+f"(d[1]), "+f"(d[2]), "+f"(d[3])
        : "r"(a[0]), "r"(a[1]), "r"(a[2]), "r"(a[3]), "r"(b[0]), "r"(b[1]));
}
__device__ __forceinline__ uint32_t packbf2(float x, float y) {
    __nv_bfloat162 t = __floats2bfloat162_rn(x, y);
    return *reinterpret_cast<uint32_t*>(&t);
}

// ---------------------------------------------------------------------------
// Fused split: fp32 -> (bf16 hi, bf16 lo); blockIdx.z selects the job.
// ---------------------------------------------------------------------------
struct SplitJobs {
    const float4*     x[4];
    __nv_bfloat162*   hi[4];
    __nv_bfloat162*   lo[4];
};

__global__ __launch_bounds__(256) void split_many_kernel(SplitJobs jobs, int n4)
{
    const int z = blockIdx.z;
    int i = blockIdx.x * 256 + threadIdx.x;
    if (i >= n4) return;
    float4 v = jobs.x[z][i];
    __nv_bfloat162 h0 = __floats2bfloat162_rn(v.x, v.y);
    __nv_bfloat162 h1 = __floats2bfloat162_rn(v.z, v.w);
    jobs.hi[z][2*i]   = h0;
    jobs.hi[z][2*i+1] = h1;
    jobs.lo[z][2*i]   = __floats2bfloat162_rn(v.x - __low2float(h0), v.y - __high2float(h0));
    jobs.lo[z][2*i+1] = __floats2bfloat162_rn(v.z - __low2float(h1), v.w - __high2float(h1));
}

// ---------------------------------------------------------------------------
// HMMA bf16x3 GEMM (NT), fused over blockIdx.z jobs:
//   acc = sum_k A[i,k]*W[j,k]; out = (acc + bias[j]) * scale
// Output fp32 (Cf) or bf16 hi/lo (Ch,Cl).
// CTA tile 128x128; K-chunk 32 (SW64 swizzle); 3-stage cp.async ring;
// 8 warps = 2(m) x 4(n), warp tile 64x32 via m16n8k16; occupancy 2.
// ---------------------------------------------------------------------------
struct GemmJobs {
    const __nv_bfloat16 *Ah[3], *Al[3], *Bh[3], *Bl[3];
    const float* bias[3];
    __nv_bfloat16 *Ch[3], *Cl[3];
    float* Cf[3];
    float scale[3];
};

#define GTILE  8192                    // one tile chunk: 128 rows x 64B
#define GBUF   (4*GTILE)               // Ah,Al,Bh,Bl = 32 KB
#define GEMM_SMEM (3*GBUF + 1024)      // 3 stages + align pad

__global__ __launch_bounds__(256, 2) void gemm_tc_kernel(GemmJobs j)
{
    extern __shared__ char smem[];
    const uint32_t sbase = (smem_u32(smem) + 1023u) & ~1023u;
    const int z   = blockIdx.z;
    const int tid = threadIdx.x;
    const int wid = tid >> 5;
    const int lid = tid & 31;
    const int wm  = wid >> 2;          // 0..1
    const int wn  = wid & 3;           // 0..3
    const int nBase = blockIdx.x * 128;
    const int mBase = blockIdx.y * 128;

    const uint4* srcs[4] = {
        reinterpret_cast<const uint4*>(j.Ah[z]) + (size_t)mBase * 128,
        reinterpret_cast<const uint4*>(j.Al[z]) + (size_t)mBase * 128,
        reinterpret_cast<const uint4*>(j.Bh[z]) + (size_t)nBase * 128,
        reinterpret_cast<const uint4*>(j.Bl[z]) + (size_t)nBase * 128
    };

    // one K-chunk (32 bf16 = 4 uint4 per row) into stage buffer at bufAddr
    auto load_chunk = [&](int ch, uint32_t bufAddr) {
        const int kq = ch * 4;
#pragma unroll
        for (int t = 0; t < 8; t++) {
            const int tile = t >> 1;
            const int i = tid + (t & 1) * 256;   // 0..511
            const int r = i >> 2, c = i & 3;
            const uint4* src = srcs[tile] + (size_t)r * 128 + kq + c;
            uint32_t dst = bufAddr + tile * GTILE + SWZ64(r * 64 + c * 16);
            CP_ASYNC16(dst, src);
        }
        CP_COMMIT();
    };

    float acc[4][4][4];
#pragma unroll
    for (int mt = 0; mt < 4; mt++)
#pragma unroll
        for (int nt = 0; nt < 4; nt++)
#pragma unroll
            for (int r = 0; r < 4; r++) acc[mt][nt][r] = 0.f;

    load_chunk(0, sbase);
    load_chunk(1, sbase + GBUF);

    // chunk-invariant fragment address components
    const int aRow   = wm * 64 + (lid & 15);
    const int aColH  = (lid >> 4) * 16;
    const int bRow16 = wn * 32 + (lid & 7) + 8 * ((lid >> 4) & 1);
    const int bColH  = ((lid >> 3) & 1) * 16;

    int stage = 0;
#pragma unroll 1
    for (int ch = 0; ch < 32; ch++) {
        if (ch < 30) { CP_WAIT1(); } else { CP_WAIT0(); }
        __syncthreads();
        if (ch < 30) {
            int nst = stage + 2; if (nst >= 3) nst -= 3;
            load_chunk(ch + 2, sbase + nst * GBUF);
        }

        const uint32_t bufAddr = sbase + stage * GBUF;
#pragma unroll
        for (int ks = 0; ks < 2; ks++) {
            uint32_t bh[2][4], bl[2][4];
#pragma unroll
            for (int ntp = 0; ntp < 2; ntp++) {
                uint32_t off = SWZ64((bRow16 + ntp * 16) * 64 + ks * 32 + bColH);
                ldsm_x4(bh[ntp], bufAddr + 2 * GTILE + off);
                ldsm_x4(bl[ntp], bufAddr + 3 * GTILE + off);
            }
#pragma unroll
            for (int mt = 0; mt < 4; mt++) {
                uint32_t ah[4], al[4];
                uint32_t offA = SWZ64((aRow + mt * 16) * 64 + ks * 32 + aColH);
                ldsm_x4(ah, bufAddr + offA);
                ldsm_x4(al, bufAddr + GTILE + offA);
#pragma unroll
                for (int nt = 0; nt < 4; nt++) {
                    const uint32_t* bhp = &bh[nt >> 1][(nt & 1) * 2];
                    const uint32_t* blp = &bl[nt >> 1][(nt & 1) * 2];
                    mma16816(acc[mt][nt], ah, bhp);
                    mma16816(acc[mt][nt], ah, blp);
                    mma16816(acc[mt][nt], al, bhp);
                }
            }
        }
        if (++stage == 3) stage = 0;
    }

    // Epilogue
    const float scale = j.scale[z];
    const float* bias = j.bias[z];
    float* Cf = j.Cf[z];
    __nv_bfloat16* Ch = j.Ch[z];
    __nv_bfloat16* Cl = j.Cl[z];
    const int erow = mBase + wm * 64 + (lid >> 2);
    const int ecolBase = nBase + wn * 32 + 2 * (lid & 3);
#pragma unroll
    for (int nt = 0; nt < 4; nt++) {
        const int col = ecolBase + nt * 8;
        const float b0 = __ldg(bias + col), b1 = __ldg(bias + col + 1);
#pragma unroll
        for (int mt = 0; mt < 4; mt++) {
            const int r0 = erow + mt * 16;
            float v0 = (acc[mt][nt][0] + b0) * scale;
            float v1 = (acc[mt][nt][1] + b1) * scale;
            float v2 = (acc[mt][nt][2] + b0) * scale;
            float v3 = (acc[mt][nt][3] + b1) * scale;
            if (Cf) {
                *reinterpret_cast<float2*>(Cf + (size_t)r0 * DD + col)       = make_float2(v0, v1);
                *reinterpret_cast<float2*>(Cf + (size_t)(r0 + 8) * DD + col) = make_float2(v2, v3);
            } else {
                __nv_bfloat162 h0 = __floats2bfloat162_rn(v0, v1);
                __nv_bfloat162 h1 = __floats2bfloat162_rn(v2, v3);
                *reinterpret_cast<__nv_bfloat162*>(Ch + (size_t)r0 * DD + col)       = h0;
                *reinterpret_cast<__nv_bfloat162*>(Ch + (size_t)(r0 + 8) * DD + col) = h1;
                *reinterpret_cast<__nv_bfloat162*>(Cl + (size_t)r0 * DD + col) =
                    __floats2bfloat162_rn(v0 - __low2float(h0), v1 - __high2float(h0));
                *reinterpret_cast<__nv_bfloat162*>(Cl + (size_t)(r0 + 8) * DD + col) =
                    __floats2bfloat162_rn(v2 - __low2float(h1), v3 - __high2float(h1));
            }
        }
    }
}

// ---------------------------------------------------------------------------
// MMA flash attention. Q pre-scaled by 1/8. All operands bf16 hi/lo in
// [B,S,D] layout (head h = cols h*64..+63). Output -> (Oh,Ol) bf16 hi/lo.
// CTA: 128 query rows x one (b,h); 8 warps x 16 rows; BK=32 keys/iter.
// scores = Qh*Kh + Qh*Kl + Ql*Kh ; PV = Ph*Vh + Ph*Vl + Pl*Vh (fp32 acc).
// K/V fragments via ldmatrix.x4 (two n8 frags per instruction).
// ---------------------------------------------------------------------------
#define KV_BYTES 16384                 // Kh,Kl,Vh,Vl 32x128B each
#define ATT_SMEM (32768 + 2*KV_BYTES + 1024)

__global__ __launch_bounds__(256, 2) void attn_mma_kernel(
    const __nv_bfloat16* __restrict__ Qh, const __nv_bfloat16* __restrict__ Ql,
    const __nv_bfloat16* __restrict__ Kh, const __nv_bfloat16* __restrict__ Kl,
    const __nv_bfloat16* __restrict__ Vh, const __nv_bfloat16* __restrict__ Vl,
    __nv_bfloat16* __restrict__ Oh, __nv_bfloat16* __restrict__ Ol)
{
    extern __shared__ char smem[];
    const uint32_t sb = (smem_u32(smem) + 1023u) & ~1023u;
    const int tid = threadIdx.x;
    const int wid = tid >> 5;
    const int lid = tid & 31;
    const int bh  = blockIdx.y;
    const int b   = bh >> 4, h = bh & 15;
    const int qBase = blockIdx.x * 128;

    const uint32_t QH_OFF = 0, QL_OFF = 16384, KV_OFF = 32768;
    const size_t qOrg = (size_t)(b * SS + qBase) * DD + h * DKK;
    const size_t kOrg = (size_t)(b * SS) * DD + h * DKK;

    // stage Q (hi/lo): 2 x 128 rows x 8 chunks of 16B
    {
#pragma unroll
        for (int jj = 0; jj < 8; jj++) {
            int i  = tid + jj * 256;
            int sp = i >> 10;
            int r  = (i & 1023) >> 3;
            int c  = i & 7;
            const __nv_bfloat16* src = (sp ? Ql : Qh) + qOrg + (size_t)r * DD + c * 8;
            uint32_t dst = sb + (sp ? QL_OFF : QH_OFF) + SWZ128(r * 128 + c * 16);
            CP_ASYNC16(dst, src);
        }
    }
    const __nv_bfloat16* kvsrc[4] = { Kh, Kl, Vh, Vl };
    auto load_kv = [&](int t, int buf) {
        const int r = tid >> 3, c = tid & 7;
        const size_t g = kOrg + (size_t)(t * 32 + r) * DD + c * 8;
        const uint32_t dstb = sb + KV_OFF + buf * KV_BYTES + SWZ128(r * 128 + c * 16);
#pragma unroll
        for (int tile = 0; tile < 4; tile++)
            CP_ASYNC16(dstb + tile * 4096, kvsrc[tile] + g);
        CP_COMMIT();
    };

    load_kv(0, 0);
    CP_WAIT0();
    __syncthreads();

    // Q fragments (persist in registers)
    uint32_t qfh[4][4], qfl[4][4];
    {
        const int aRow = wid * 16 + (lid & 15);
        const int aColH = (lid >> 4) * 16;
#pragma unroll
        for (int ks = 0; ks < 4; ks++) {
            uint32_t off = SWZ128(aRow * 128 + ks * 32 + aColH);
            ldsm_x4(qfh[ks], sb + QH_OFF + off);
            ldsm_x4(qfl[ks], sb + QL_OFF + off);
        }
    }

    float o[8][4];
#pragma unroll
    for (int nt = 0; nt < 8; nt++)
#pragma unroll
        for (int r = 0; r < 4; r++) o[nt][r] = 0.f;
    float m0 = -1e30f, m1 = -1e30f, l0 = 0.f, l1 = 0.f;

    // x4 fragment address components
    const int kRow  = (lid & 7) + 8 * ((lid >> 4) & 1);     // + ntp*16
    const int kColH = ((lid >> 3) & 1) * 16;                // + ks*32
    const int vRow  = (lid & 7) + 8 * ((lid >> 3) & 1);     // + ks*16
    const int vColH = ((lid >> 4) & 1) * 16;                // + ntp*32

#pragma unroll 1
    for (int t = 0; t < SS / 32; t++) {
        const int cur = t & 1;
        if (t < SS / 32 - 1) load_kv(t + 1, cur ^ 1);

        const uint32_t kb = sb + KV_OFF + cur * KV_BYTES;

        // scores: m16 x n32 x k64, bf16x3
        float s[4][4];
#pragma unroll
        for (int nt = 0; nt < 4; nt++)
#pragma unroll
            for (int r = 0; r < 4; r++) s[nt][r] = 0.f;
#pragma unroll
        for (int ks = 0; ks < 4; ks++) {
#pragma unroll
            for (int ntp = 0; ntp < 2; ntp++) {
                uint32_t kbh[4], kbl[4];
                uint32_t off = SWZ128((ntp * 16 + kRow) * 128 + ks * 32 + kColH);
                ldsm_x4(kbh, kb + off);            // Kh tile @ +0
                ldsm_x4(kbl, kb + 4096 + off);     // Kl tile
                mma16816(s[2*ntp],   qfh[ks], &kbh[0]);
                mma16816(s[2*ntp],   qfh[ks], &kbl[0]);
                mma16816(s[2*ntp],   qfl[ks], &kbh[0]);
                mma16816(s[2*ntp+1], qfh[ks], &kbh[2]);
                mma16816(s[2*ntp+1], qfh[ks], &kbl[2]);
                mma16816(s[2*ntp+1], qfl[ks], &kbh[2]);
            }
        }

        // online softmax (rows r=lid>>2 and r+8; cols across lanes lid&3)
        float t0 = -1e30f, t1 = -1e30f;
#pragma unroll
        for (int nt = 0; nt < 4; nt++) {
            t0 = fmaxf(t0, fmaxf(s[nt][0], s[nt][1]));
            t1 = fmaxf(t1, fmaxf(s[nt][2], s[nt][3]));
        }
        t0 = fmaxf(t0, __shfl_xor_sync(0xffffffffu, t0, 1));
        t0 = fmaxf(t0, __shfl_xor_sync(0xffffffffu, t0, 2));
        t1 = fmaxf(t1, __shfl_xor_sync(0xffffffffu, t1, 1));
        t1 = fmaxf(t1, __shfl_xor_sync(0xffffffffu, t1, 2));
        const float mn0 = fmaxf(m0, t0), mn1 = fmaxf(m1, t1);
        const float c0 = __expf(m0 - mn0), c1 = __expf(m1 - mn1);
        m0 = mn0; m1 = mn1;

        uint32_t aPh[2][4], aPl[2][4];
        float rs0 = 0.f, rs1 = 0.f;
#pragma unroll
        for (int nt = 0; nt < 4; nt++) {
            float p0 = __expf(s[nt][0] - m0);
            float p1 = __expf(s[nt][1] - m0);
            float p2 = __expf(s[nt][2] - m1);
            float p3 = __expf(s[nt][3] - m1);
            rs0 += p0 + p1; rs1 += p2 + p3;
            const int ks = nt >> 1, pos = (nt & 1) * 2;
            __nv_bfloat162 hA = __floats2bfloat162_rn(p0, p1);
            __nv_bfloat162 hB = __floats2bfloat162_rn(p2, p3);
            aPh[ks][pos]     = *reinterpret_cast<uint32_t*>(&hA);
            aPh[ks][pos + 1] = *reinterpret_cast<uint32_t*>(&hB);
            aPl[ks][pos]     = packbf2(p0 - __low2float(hA), p1 - __high2float(hA));
            aPl[ks][pos + 1] = packbf2(p2 - __low2float(hB), p3 - __high2float(hB));
        }
        rs0 += __shfl_xor_sync(0xffffffffu, rs0, 1);
        rs0 += __shfl_xor_sync(0xffffffffu, rs0, 2);
        rs1 += __shfl_xor_sync(0xffffffffu, rs1, 1);
        rs1 += __shfl_xor_sync(0xffffffffu, rs1, 2);
        l0 = l0 * c0 + rs0;
        l1 = l1 * c1 + rs1;

#pragma unroll
        for (int nt = 0; nt < 8; nt++) {
            o[nt][0] *= c0; o[nt][1] *= c0;
            o[nt][2] *= c1; o[nt][3] *= c1;
        }

        // PV: m16 x n64 x k32, bf16x3 (V via ldmatrix.x4.trans)
#pragma unroll
        for (int ks = 0; ks < 2; ks++) {
#pragma unroll
            for (int ntp = 0; ntp < 4; ntp++) {
                uint32_t vbh[4], vbl[4];
                uint32_t off = SWZ128((ks * 16 + vRow) * 128 + ntp * 32 + vColH);
                ldsm_x4t(vbh, kb + 8192 + off);     // Vh tile
                ldsm_x4t(vbl, kb + 12288 + off);    // Vl tile
                mma16816(o[2*ntp],   aPh[ks], &vbh[0]);
                mma16816(o[2*ntp],   aPh[ks], &vbl[0]);
                mma16816(o[2*ntp],   aPl[ks], &vbh[0]);
                mma16816(o[2*ntp+1], aPh[ks], &vbh[2]);
                mma16816(o[2*ntp+1], aPh[ks], &vbl[2]);
                mma16816(o[2*ntp+1], aPl[ks], &vbh[2]);
            }
        }

        CP_WAIT0();
        __syncthreads();
    }

    // epilogue: normalize, split to bf16 hi/lo, write [B,S,D]
    const float i0 = 1.f / l0, i1 = 1.f / l1;
    const size_t row0 = (size_t)(b * SS + qBase + wid * 16 + (lid >> 2));
    const int colBase = h * DKK + 2 * (lid & 3);
#pragma unroll
    for (int nt = 0; nt < 8; nt++) {
        const int col = colBase + nt * 8;
        float v0 = o[nt][0] * i0, v1 = o[nt][1] * i0;
        float v2 = o[nt][2] * i1, v3 = o[nt][3] * i1;
        __nv_bfloat162 h0 = __floats2bfloat162_rn(v0, v1);
        __nv_bfloat162 h1 = __floats2bfloat162_rn(v2, v3);
        *reinterpret_cast<__nv_bfloat162*>(Oh + row0 * DD + col)       = h0;
        *reinterpret_cast<__nv_bfloat162*>(Oh + (row0 + 8) * DD + col) = h1;
        *reinterpret_cast<__nv_bfloat162*>(Ol + row0 * DD + col) =
            __floats2bfloat162_rn(v0 - __low2float(h0), v1 - __high2float(h0));
        *reinterpret_cast<__nv_bfloat162*>(Ol + (row0 + 8) * DD + col) =
            __floats2bfloat162_rn(v2 - __low2float(h1), v3 - __high2float(h1));
    }
}

// ---------------------------------------------------------------------------
// kernel_launch
// ---------------------------------------------------------------------------
extern "C" void kernel_launch(void* const* d_in, const int* in_sizes, int n_in,
                              void* d_out, int out_size)
{
    const float* query = (const float*)d_in[0];
    const float* key   = (const float*)d_in[1];
    const float* value = (const float*)d_in[2];
    const float* Wq    = (const float*)d_in[3];
    const float* bq    = (const float*)d_in[4];
    const float* Wk    = (const float*)d_in[5];
    const float* bk    = (const float*)d_in[6];
    const float* Wv    = (const float*)d_in[7];
    const float* bv    = (const float*)d_in[8];
    const float* Wo    = (const float*)d_in[9];
    const float* bo    = (const float*)d_in[10];
    float* out = (float*)d_out;

    __nv_bfloat16 *qh, *ql, *kh, *kl, *vh, *vl, *oh, *ol;
    __nv_bfloat16 *aqh, *aql, *akh, *akl, *avh, *avl;
    __nv_bfloat16 *wqh, *wql, *wkh, *wkl, *wvh, *wvl, *woh, *wol;
    cudaGetSymbolAddress((void**)&qh,  g_qh);  cudaGetSymbolAddress((void**)&ql,  g_ql);
    cudaGetSymbolAddress((void**)&kh,  g_kh);  cudaGetSymbolAddress((void**)&kl,  g_kl);
    cudaGetSymbolAddress((void**)&vh,  g_vh);  cudaGetSymbolAddress((void**)&vl,  g_vl);
    cudaGetSymbolAddress((void**)&oh,  g_oh);  cudaGetSymbolAddress((void**)&ol,  g_ol);
    cudaGetSymbolAddress((void**)&aqh, g_aqh); cudaGetSymbolAddress((void**)&aql, g_aql);
    cudaGetSymbolAddress((void**)&akh, g_akh); cudaGetSymbolAddress((void**)&akl, g_akl);
    cudaGetSymbolAddress((void**)&avh, g_avh); cudaGetSymbolAddress((void**)&avl, g_avl);
    cudaGetSymbolAddress((void**)&wqh, g_wqh); cudaGetSymbolAddress((void**)&wql, g_wql);
    cudaGetSymbolAddress((void**)&wkh, g_wkh); cudaGetSymbolAddress((void**)&wkl, g_wkl);
    cudaGetSymbolAddress((void**)&wvh, g_wvh); cudaGetSymbolAddress((void**)&wvl, g_wvl);
    cudaGetSymbolAddress((void**)&woh, g_woh); cudaGetSymbolAddress((void**)&wol, g_wol);

    cudaFuncSetAttribute(gemm_tc_kernel,
                         cudaFuncAttributeMaxDynamicSharedMemorySize, GEMM_SMEM);
    cudaFuncSetAttribute(attn_mma_kernel,
                         cudaFuncAttributeMaxDynamicSharedMemorySize, ATT_SMEM);

    const int n4a = MROWS * DD / 4;   // 2097152
    const int n4w = DD * DD / 4;      // 262144

    // 1) split activations (q, k, v) — one launch, z=3
    {
        SplitJobs sj{};
        sj.x[0] = (const float4*)query; sj.hi[0] = (__nv_bfloat162*)aqh; sj.lo[0] = (__nv_bfloat162*)aql;
        sj.x[1] = (const float4*)key;   sj.hi[1] = (__nv_bfloat162*)akh; sj.lo[1] = (__nv_bfloat162*)akl;
        sj.x[2] = (const float4*)value; sj.hi[2] = (__nv_bfloat162*)avh; sj.lo[2] = (__nv_bfloat162*)avl;
        split_many_kernel<<<dim3(n4a / 256, 1, 3), 256>>>(sj, n4a);
    }
    // 2) split weights (Wq, Wk, Wv, Wo) — one launch, z=4
    {
        SplitJobs sj{};
        sj.x[0] = (const float4*)Wq; sj.hi[0] = (__nv_bfloat162*)wqh; sj.lo[0] = (__nv_bfloat162*)wql;
        sj.x[1] = (const float4*)Wk; sj.hi[1] = (__nv_bfloat162*)wkh; sj.lo[1] = (__nv_bfloat162*)wkl;
        sj.x[2] = (const float4*)Wv; sj.hi[2] = (__nv_bfloat162*)wvh; sj.lo[2] = (__nv_bfloat162*)wvl;
        sj.x[3] = (const float4*)Wo; sj.hi[3] = (__nv_bfloat162*)woh; sj.lo[3] = (__nv_bfloat162*)wol;
        split_many_kernel<<<dim3(n4w / 256, 1, 4), 256>>>(sj, n4w);
    }
    // 3) fused Q/K/V projections — one launch, z=3 (scale 1/8 folded into Q)
    {
        GemmJobs gj{};
        gj.Ah[0] = aqh; gj.Al[0] = aql; gj.Bh[0] = wqh; gj.Bl[0] = wql;
        gj.bias[0] = bq; gj.Ch[0] = qh; gj.Cl[0] = ql; gj.Cf[0] = nullptr; gj.scale[0] = 0.125f;
        gj.Ah[1] = akh; gj.Al[1] = akl; gj.Bh[1] = wkh; gj.Bl[1] = wkl;
        gj.bias[1] = bk; gj.Ch[1] = kh; gj.Cl[1] = kl; gj.Cf[1] = nullptr; gj.scale[1] = 1.0f;
        gj.Ah[2] = avh; gj.Al[2] = avl; gj.Bh[2] = wvh; gj.Bl[2] = wvl;
        gj.bias[2] = bv; gj.Ch[2] = vh; gj.Cl[2] = vl; gj.Cf[2] = nullptr; gj.scale[2] = 1.0f;
        gemm_tc_kernel<<<dim3(DD / 128, MROWS / 128, 3), 256, GEMM_SMEM>>>(gj);
    }
    // 4) attention -> (oh, ol)
    attn_mma_kernel<<<dim3(SS / 128, BB * HH), 256, ATT_SMEM>>>(qh, ql, kh, kl, vh, vl, oh, ol);
    // 5) output projection -> fp32 d_out
    {
        GemmJobs gj{};
        gj.Ah[0] = oh; gj.Al[0] = ol; gj.Bh[0] = woh; gj.Bl[0] = wol;
        gj.bias[0] = bo; gj.Ch[0] = nullptr; gj.Cl[0] = nullptr; gj.Cf[0] = out; gj.scale[0] = 1.0f;
        gemm_tc_kernel<<<dim3(DD / 128, MROWS / 128, 1), 256, GEMM_SMEM>>>(gj);
    }
}

// round 16
// speedup vs baseline: 1.5816x; 1.0003x over previous
#include <cuda_runtime.h>
#include <cuda_bf16.h>
#include <cstdint>

// Problem constants
#define BB 4
#define SS 2048
#define DD 1024
#define HH 16
#define DKK 64
#define MROWS (BB*SS)          // 8192

// ---------------------------------------------------------------------------
// Scratch (device globals — no allocations allowed)
// ---------------------------------------------------------------------------
__device__ __nv_bfloat16 g_qh[MROWS*DD], g_ql[MROWS*DD];     // Q proj out (pre-scaled 1/8)
__device__ __nv_bfloat16 g_kh[MROWS*DD], g_kl[MROWS*DD];     // K proj out
__device__ __nv_bfloat16 g_vh[MROWS*DD], g_vl[MROWS*DD];     // V proj out
__device__ __nv_bfloat16 g_aqh[MROWS*DD], g_aql[MROWS*DD];   // activation splits
__device__ __nv_bfloat16 g_akh[MROWS*DD], g_akl[MROWS*DD];
__device__ __nv_bfloat16 g_avh[MROWS*DD], g_avl[MROWS*DD];
__device__ __nv_bfloat16 g_oh[MROWS*DD],  g_ol[MROWS*DD];    // attention out
__device__ __nv_bfloat16 g_wqh[DD*DD], g_wql[DD*DD];         // weight splits
__device__ __nv_bfloat16 g_wkh[DD*DD], g_wkl[DD*DD];
__device__ __nv_bfloat16 g_wvh[DD*DD], g_wvl[DD*DD];
__device__ __nv_bfloat16 g_woh[DD*DD], g_wol[DD*DD];

// ---------------------------------------------------------------------------
// Helpers
// ---------------------------------------------------------------------------
__device__ __forceinline__ uint32_t smem_u32(const void* p) {
    uint32_t a;
    asm("{ .reg .u64 t; cvta.to.shared.u64 t, %1; cvt.u32.u64 %0, t; }" : "=r"(a) : "l"(p));
    return a;
}
#define SWZ128(o) ((o) ^ (((o) >> 3) & 0x70))
#define SWZ64(o)  ((o) ^ (((o) >> 3) & 0x30))

#define CP_ASYNC16(dst, src) \
    asm volatile("cp.async.cg.shared.global [%0], [%1], 16;" :: "r"(dst), "l"(src))
#define CP_COMMIT()  asm volatile("cp.async.commit_group;" ::: "memory")
#define CP_WAIT0()   asm volatile("cp.async.wait_group 0;" ::: "memory")
#define CP_WAIT1()   asm volatile("cp.async.wait_group 1;" ::: "memory")

__device__ __forceinline__ void ldsm_x4(uint32_t* r, uint32_t addr) {
    asm volatile("ldmatrix.sync.aligned.m8n8.x4.shared.b16 {%0,%1,%2,%3}, [%4];"
        : "=r"(r[0]), "=r"(r[1]), "=r"(r[2]), "=r"(r[3]) : "r"(addr));
}
__device__ __forceinline__ void ldsm_x4t(uint32_t* r, uint32_t addr) {
    asm volatile("ldmatrix.sync.aligned.m8n8.x4.trans.shared.b16 {%0,%1,%2,%3}, [%4];"
        : "=r"(r[0]), "=r"(r[1]), "=r"(r[2]), "=r"(r[3]) : "r"(addr));
}
__device__ __forceinline__ void mma16816(float* d, const uint32_t* a, const uint32_t* b) {
    asm volatile("mma.sync.aligned.m16n8k16.row.col.f32.bf16.bf16.f32 "
        "{%0,%1,%2,%3}, {%4,%5,%6,%7}, {%8,%9}, {%0,%1,%2,%3};"
        : "+f"(d[0]), "+f"(d[1]), "+f"(d[2]), "+f"(d[3])
        : "r"(a[0]), "r"(a[1]), "r"(a[2]), "r"(a[3]), "r"(b[0]), "r"(b[1]));
}
__device__ __forceinline__ uint32_t packbf2(float x, float y) {
    __nv_bfloat162 t = __floats2bfloat162_rn(x, y);
    return *reinterpret_cast<uint32_t*>(&t);
}

// ---------------------------------------------------------------------------
// Fused split: fp32 -> (bf16 hi, bf16 lo); blockIdx.z selects the job.
// ---------------------------------------------------------------------------
struct SplitJobs {
    const float4*     x[4];
    __nv_bfloat162*   hi[4];
    __nv_bfloat162*   lo[4];
};

__global__ __launch_bounds__(256) void split_many_kernel(SplitJobs jobs, int n4)
{
    const int z = blockIdx.z;
    int i = blockIdx.x * 256 + threadIdx.x;
    if (i >= n4) return;
    float4 v = jobs.x[z][i];
    __nv_bfloat162 h0 = __floats2bfloat162_rn(v.x, v.y);
    __nv_bfloat162 h1 = __floats2bfloat162_rn(v.z, v.w);
    jobs.hi[z][2*i]   = h0;
    jobs.hi[z][2*i+1] = h1;
    jobs.lo[z][2*i]   = __floats2bfloat162_rn(v.x - __low2float(h0), v.y - __high2float(h0));
    jobs.lo[z][2*i+1] = __floats2bfloat162_rn(v.z - __low2float(h1), v.w - __high2float(h1));
}

// ---------------------------------------------------------------------------
// HMMA bf16x3 GEMM (NT), fused over blockIdx.z jobs:
//   acc = sum_k A[i,k]*W[j,k]; out = (acc + bias[j]) * scale
// Output fp32 (Cf) or bf16 hi/lo (Ch,Cl).
// CTA tile 128x128; K-chunk 32 (SW64 swizzle); 3-stage cp.async ring;
// 8 warps = 2(m) x 4(n), warp tile 64x32 via m16n8k16; occupancy 2.
// ---------------------------------------------------------------------------
struct GemmJobs {
    const __nv_bfloat16 *Ah[3], *Al[3], *Bh[3], *Bl[3];
    const float* bias[3];
    __nv_bfloat16 *Ch[3], *Cl[3];
    float* Cf[3];
    float scale[3];
};

#define GTILE  8192                    // one tile chunk: 128 rows x 64B
#define GBUF   (4*GTILE)               // Ah,Al,Bh,Bl = 32 KB
#define GEMM_SMEM (3*GBUF + 1024)      // 3 stages + align pad

__global__ __launch_bounds__(256, 2) void gemm_tc_kernel(GemmJobs j)
{
    extern __shared__ char smem[];
    const uint32_t sbase = (smem_u32(smem) + 1023u) & ~1023u;
    const int z   = blockIdx.z;
    const int tid = threadIdx.x;
    const int wid = tid >> 5;
    const int lid = tid & 31;
    const int wm  = wid >> 2;          // 0..1
    const int wn  = wid & 3;           // 0..3
    const int nBase = blockIdx.x * 128;
    const int mBase = blockIdx.y * 128;

    const uint4* srcs[4] = {
        reinterpret_cast<const uint4*>(j.Ah[z]) + (size_t)mBase * 128,
        reinterpret_cast<const uint4*>(j.Al[z]) + (size_t)mBase * 128,
        reinterpret_cast<const uint4*>(j.Bh[z]) + (size_t)nBase * 128,
        reinterpret_cast<const uint4*>(j.Bl[z]) + (size_t)nBase * 128
    };

    // one K-chunk (32 bf16 = 4 uint4 per row) into stage buffer at bufAddr
    auto load_chunk = [&](int ch, uint32_t bufAddr) {
        const int kq = ch * 4;
#pragma unroll
        for (int t = 0; t < 8; t++) {
            const int tile = t >> 1;
            const int i = tid + (t & 1) * 256;   // 0..511
            const int r = i >> 2, c = i & 3;
            const uint4* src = srcs[tile] + (size_t)r * 128 + kq + c;
            uint32_t dst = bufAddr + tile * GTILE + SWZ64(r * 64 + c * 16);
            CP_ASYNC16(dst, src);
        }
        CP_COMMIT();
    };

    float acc[4][4][4];
#pragma unroll
    for (int mt = 0; mt < 4; mt++)
#pragma unroll
        for (int nt = 0; nt < 4; nt++)
#pragma unroll
            for (int r = 0; r < 4; r++) acc[mt][nt][r] = 0.f;

    load_chunk(0, sbase);
    load_chunk(1, sbase + GBUF);

    // chunk-invariant fragment address components
    const int aRow   = wm * 64 + (lid & 15);
    const int aColH  = (lid >> 4) * 16;
    const int bRow16 = wn * 32 + (lid & 7) + 8 * ((lid >> 4) & 1);
    const int bColH  = ((lid >> 3) & 1) * 16;

    int stage = 0;
#pragma unroll 1
    for (int ch = 0; ch < 32; ch++) {
        if (ch < 30) { CP_WAIT1(); } else { CP_WAIT0(); }
        __syncthreads();
        if (ch < 30) {
            int nst = stage + 2; if (nst >= 3) nst -= 3;
            load_chunk(ch + 2, sbase + nst * GBUF);
        }

        const uint32_t bufAddr = sbase + stage * GBUF;
#pragma unroll
        for (int ks = 0; ks < 2; ks++) {
            uint32_t bh[2][4], bl[2][4];
#pragma unroll
            for (int ntp = 0; ntp < 2; ntp++) {
                uint32_t off = SWZ64((bRow16 + ntp * 16) * 64 + ks * 32 + bColH);
                ldsm_x4(bh[ntp], bufAddr + 2 * GTILE + off);
                ldsm_x4(bl[ntp], bufAddr + 3 * GTILE + off);
            }
#pragma unroll
            for (int mt = 0; mt < 4; mt++) {
                uint32_t ah[4], al[4];
                uint32_t offA = SWZ64((aRow + mt * 16) * 64 + ks * 32 + aColH);
                ldsm_x4(ah, bufAddr + offA);
                ldsm_x4(al, bufAddr + GTILE + offA);
#pragma unroll
                for (int nt = 0; nt < 4; nt++) {
                    const uint32_t* bhp = &bh[nt >> 1][(nt & 1) * 2];
                    const uint32_t* blp = &bl[nt >> 1][(nt & 1) * 2];
                    mma16816(acc[mt][nt], ah, bhp);
                    mma16816(acc[mt][nt], ah, blp);
                    mma16816(acc[mt][nt], al, bhp);
                }
            }
        }
        if (++stage == 3) stage = 0;
    }

    // Epilogue
    const float scale = j.scale[z];
    const float* bias = j.bias[z];
    float* Cf = j.Cf[z];
    __nv_bfloat16* Ch = j.Ch[z];
    __nv_bfloat16* Cl = j.Cl[z];
    const int erow = mBase + wm * 64 + (lid >> 2);
    const int ecolBase = nBase + wn * 32 + 2 * (lid & 3);
#pragma unroll
    for (int nt = 0; nt < 4; nt++) {
        const int col = ecolBase + nt * 8;
        const float b0 = __ldg(bias + col), b1 = __ldg(bias + col + 1);
#pragma unroll
        for (int mt = 0; mt < 4; mt++) {
            const int r0 = erow + mt * 16;
            float v0 = (acc[mt][nt][0] + b0) * scale;
            float v1 = (acc[mt][nt][1] + b1) * scale;
            float v2 = (acc[mt][nt][2] + b0) * scale;
            float v3 = (acc[mt][nt][3] + b1) * scale;
            if (Cf) {
                *reinterpret_cast<float2*>(Cf + (size_t)r0 * DD + col)       = make_float2(v0, v1);
                *reinterpret_cast<float2*>(Cf + (size_t)(r0 + 8) * DD + col) = make_float2(v2, v3);
            } else {
                __nv_bfloat162 h0 = __floats2bfloat162_rn(v0, v1);
                __nv_bfloat162 h1 = __floats2bfloat162_rn(v2, v3);
                *reinterpret_cast<__nv_bfloat162*>(Ch + (size_t)r0 * DD + col)       = h0;
                *reinterpret_cast<__nv_bfloat162*>(Ch + (size_t)(r0 + 8) * DD + col) = h1;
                *reinterpret_cast<__nv_bfloat162*>(Cl + (size_t)r0 * DD + col) =
                    __floats2bfloat162_rn(v0 - __low2float(h0), v1 - __high2float(h0));
                *reinterpret_cast<__nv_bfloat162*>(Cl + (size_t)(r0 + 8) * DD + col) =
                    __floats2bfloat162_rn(v2 - __low2float(h1), v3 - __high2float(h1));
            }
        }
    }
}

// ---------------------------------------------------------------------------
// MMA flash attention. Q pre-scaled by 1/8. All operands bf16 hi/lo in
// [B,S,D] layout (head h = cols h*64..+63). Output -> (Oh,Ol) bf16 hi/lo.
// CTA: 128 query rows x one (b,h); 8 warps x 16 rows; BK=32 keys/iter.
// scores = Qh*Kh + Qh*Kl + Ql*Kh ; PV = Ph*Vh + Ph*Vl + Pl*Vh (fp32 acc).
// K/V fragments via ldmatrix.x4 (two n8 frags per instruction).
// ---------------------------------------------------------------------------
#define KV_BYTES 16384                 // Kh,Kl,Vh,Vl 32x128B each
#define ATT_SMEM (32768 + 2*KV_BYTES + 1024)

__global__ __launch_bounds__(256, 2) void attn_mma_kernel(
    const __nv_bfloat16* __restrict__ Qh, const __nv_bfloat16* __restrict__ Ql,
    const __nv_bfloat16* __restrict__ Kh, const __nv_bfloat16* __restrict__ Kl,
    const __nv_bfloat16* __restrict__ Vh, const __nv_bfloat16* __restrict__ Vl,
    __nv_bfloat16* __restrict__ Oh, __nv_bfloat16* __restrict__ Ol)
{
    extern __shared__ char smem[];
    const uint32_t sb = (smem_u32(smem) + 1023u) & ~1023u;
    const int tid = threadIdx.x;
    const int wid = tid >> 5;
    const int lid = tid & 31;
    const int bh  = blockIdx.y;
    const int b   = bh >> 4, h = bh & 15;
    const int qBase = blockIdx.x * 128;

    const uint32_t QH_OFF = 0, QL_OFF = 16384, KV_OFF = 32768;
    const size_t qOrg = (size_t)(b * SS + qBase) * DD + h * DKK;
    const size_t kOrg = (size_t)(b * SS) * DD + h * DKK;

    // stage Q (hi/lo): 2 x 128 rows x 8 chunks of 16B
    {
#pragma unroll
        for (int jj = 0; jj < 8; jj++) {
            int i  = tid + jj * 256;
            int sp = i >> 10;
            int r  = (i & 1023) >> 3;
            int c  = i & 7;
            const __nv_bfloat16* src = (sp ? Ql : Qh) + qOrg + (size_t)r * DD + c * 8;
            uint32_t dst = sb + (sp ? QL_OFF : QH_OFF) + SWZ128(r * 128 + c * 16);
            CP_ASYNC16(dst, src);
        }
    }
    const __nv_bfloat16* kvsrc[4] = { Kh, Kl, Vh, Vl };
    auto load_kv = [&](int t, int buf) {
        const int r = tid >> 3, c = tid & 7;
        const size_t g = kOrg + (size_t)(t * 32 + r) * DD + c * 8;
        const uint32_t dstb = sb + KV_OFF + buf * KV_BYTES + SWZ128(r * 128 + c * 16);
#pragma unroll
        for (int tile = 0; tile < 4; tile++)
            CP_ASYNC16(dstb + tile * 4096, kvsrc[tile] + g);
        CP_COMMIT();
    };

    load_kv(0, 0);
    CP_WAIT0();
    __syncthreads();

    // Q fragments (persist in registers)
    uint32_t qfh[4][4], qfl[4][4];
    {
        const int aRow = wid * 16 + (lid & 15);
        const int aColH = (lid >> 4) * 16;
#pragma unroll
        for (int ks = 0; ks < 4; ks++) {
            uint32_t off = SWZ128(aRow * 128 + ks * 32 + aColH);
            ldsm_x4(qfh[ks], sb + QH_OFF + off);
            ldsm_x4(qfl[ks], sb + QL_OFF + off);
        }
    }

    float o[8][4];
#pragma unroll
    for (int nt = 0; nt < 8; nt++)
#pragma unroll
        for (int r = 0; r < 4; r++) o[nt][r] = 0.f;
    float m0 = -1e30f, m1 = -1e30f, l0 = 0.f, l1 = 0.f;

    // x4 fragment address components
    const int kRow  = (lid & 7) + 8 * ((lid >> 4) & 1);     // + ntp*16
    const int kColH = ((lid >> 3) & 1) * 16;                // + ks*32
    const int vRow  = (lid & 7) + 8 * ((lid >> 3) & 1);     // + ks*16
    const int vColH = ((lid >> 4) & 1) * 16;                // + ntp*32

#pragma unroll 1
    for (int t = 0; t < SS / 32; t++) {
        const int cur = t & 1;
        if (t < SS / 32 - 1) load_kv(t + 1, cur ^ 1);

        const uint32_t kb = sb + KV_OFF + cur * KV_BYTES;

        // scores: m16 x n32 x k64, bf16x3
        float s[4][4];
#pragma unroll
        for (int nt = 0; nt < 4; nt++)
#pragma unroll
            for (int r = 0; r < 4; r++) s[nt][r] = 0.f;
#pragma unroll
        for (int ks = 0; ks < 4; ks++) {
#pragma unroll
            for (int ntp = 0; ntp < 2; ntp++) {
                uint32_t kbh[4], kbl[4];
                uint32_t off = SWZ128((ntp * 16 + kRow) * 128 + ks * 32 + kColH);
                ldsm_x4(kbh, kb + off);            // Kh tile @ +0
                ldsm_x4(kbl, kb + 4096 + off);     // Kl tile
                mma16816(s[2*ntp],   qfh[ks], &kbh[0]);
                mma16816(s[2*ntp],   qfh[ks], &kbl[0]);
                mma16816(s[2*ntp],   qfl[ks], &kbh[0]);
                mma16816(s[2*ntp+1], qfh[ks], &kbh[2]);
                mma16816(s[2*ntp+1], qfh[ks], &kbl[2]);
                mma16816(s[2*ntp+1], qfl[ks], &kbh[2]);
            }
        }

        // online softmax (rows r=lid>>2 and r+8; cols across lanes lid&3)
        float t0 = -1e30f, t1 = -1e30f;
#pragma unroll
        for (int nt = 0; nt < 4; nt++) {
            t0 = fmaxf(t0, fmaxf(s[nt][0], s[nt][1]));
            t1 = fmaxf(t1, fmaxf(s[nt][2], s[nt][3]));
        }
        t0 = fmaxf(t0, __shfl_xor_sync(0xffffffffu, t0, 1));
        t0 = fmaxf(t0, __shfl_xor_sync(0xffffffffu, t0, 2));
        t1 = fmaxf(t1, __shfl_xor_sync(0xffffffffu, t1, 1));
        t1 = fmaxf(t1, __shfl_xor_sync(0xffffffffu, t1, 2));
        const float mn0 = fmaxf(m0, t0), mn1 = fmaxf(m1, t1);
        const float c0 = __expf(m0 - mn0), c1 = __expf(m1 - mn1);
        m0 = mn0; m1 = mn1;

        uint32_t aPh[2][4], aPl[2][4];
        float rs0 = 0.f, rs1 = 0.f;
#pragma unroll
        for (int nt = 0; nt < 4; nt++) {
            float p0 = __expf(s[nt][0] - m0);
            float p1 = __expf(s[nt][1] - m0);
            float p2 = __expf(s[nt][2] - m1);
            float p3 = __expf(s[nt][3] - m1);
            rs0 += p0 + p1; rs1 += p2 + p3;
            const int ks = nt >> 1, pos = (nt & 1) * 2;
            __nv_bfloat162 hA = __floats2bfloat162_rn(p0, p1);
            __nv_bfloat162 hB = __floats2bfloat162_rn(p2, p3);
            aPh[ks][pos]     = *reinterpret_cast<uint32_t*>(&hA);
            aPh[ks][pos + 1] = *reinterpret_cast<uint32_t*>(&hB);
            aPl[ks][pos]     = packbf2(p0 - __low2float(hA), p1 - __high2float(hA));
            aPl[ks][pos + 1] = packbf2(p2 - __low2float(hB), p3 - __high2float(hB));
        }
        rs0 += __shfl_xor_sync(0xffffffffu, rs0, 1);
        rs0 += __shfl_xor_sync(0xffffffffu, rs0, 2);
        rs1 += __shfl_xor_sync(0xffffffffu, rs1, 1);
        rs1 += __shfl_xor_sync(0xffffffffu, rs1, 2);
        l0 = l0 * c0 + rs0;
        l1 = l1 * c1 + rs1;

#pragma unroll
        for (int nt = 0; nt < 8; nt++) {
            o[nt][0] *= c0; o[nt][1] *= c0;
            o[nt][2] *= c1; o[nt][3] *= c1;
        }

        // PV: m16 x n64 x k32, bf16x3 (V via ldmatrix.x4.trans)
#pragma unroll
        for (int ks = 0; ks < 2; ks++) {
#pragma unroll
            for (int ntp = 0; ntp < 4; ntp++) {
                uint32_t vbh[4], vbl[4];
                uint32_t off = SWZ128((ks * 16 + vRow) * 128 + ntp * 32 + vColH);
                ldsm_x4t(vbh, kb + 8192 + off);     // Vh tile
                ldsm_x4t(vbl, kb + 12288 + off);    // Vl tile
                mma16816(o[2*ntp],   aPh[ks], &vbh[0]);
                mma16816(o[2*ntp],   aPh[ks], &vbl[0]);
                mma16816(o[2*ntp],   aPl[ks], &vbh[0]);
                mma16816(o[2*ntp+1], aPh[ks], &vbh[2]);
                mma16816(o[2*ntp+1], aPh[ks], &vbl[2]);
                mma16816(o[2*ntp+1], aPl[ks], &vbh[2]);
            }
        }

        CP_WAIT0();
        __syncthreads();
    }

    // epilogue: normalize, split to bf16 hi/lo, write [B,S,D]
    const float i0 = 1.f / l0, i1 = 1.f / l1;
    const size_t row0 = (size_t)(b * SS + qBase + wid * 16 + (lid >> 2));
    const int colBase = h * DKK + 2 * (lid & 3);
#pragma unroll
    for (int nt = 0; nt < 8; nt++) {
        const int col = colBase + nt * 8;
        float v0 = o[nt][0] * i0, v1 = o[nt][1] * i0;
        float v2 = o[nt][2] * i1, v3 = o[nt][3] * i1;
        __nv_bfloat162 h0 = __floats2bfloat162_rn(v0, v1);
        __nv_bfloat162 h1 = __floats2bfloat162_rn(v2, v3);
        *reinterpret_cast<__nv_bfloat162*>(Oh + row0 * DD + col)       = h0;
        *reinterpret_cast<__nv_bfloat162*>(Oh + (row0 + 8) * DD + col) = h1;
        *reinterpret_cast<__nv_bfloat162*>(Ol + row0 * DD + col) =
            __floats2bfloat162_rn(v0 - __low2float(h0), v1 - __high2float(h0));
        *reinterpret_cast<__nv_bfloat162*>(Ol + (row0 + 8) * DD + col) =
            __floats2bfloat162_rn(v2 - __low2float(h1), v3 - __high2float(h1));
    }
}

// ---------------------------------------------------------------------------
// kernel_launch
// ---------------------------------------------------------------------------
extern "C" void kernel_launch(void* const* d_in, const int* in_sizes, int n_in,
                              void* d_out, int out_size)
{
    const float* query = (const float*)d_in[0];
    const float* key   = (const float*)d_in[1];
    const float* value = (const float*)d_in[2];
    const float* Wq    = (const float*)d_in[3];
    const float* bq    = (const float*)d_in[4];
    const float* Wk    = (const float*)d_in[5];
    const float* bk    = (const float*)d_in[6];
    const float* Wv    = (const float*)d_in[7];
    const float* bv    = (const float*)d_in[8];
    const float* Wo    = (const float*)d_in[9];
    const float* bo    = (const float*)d_in[10];
    float* out = (float*)d_out;

    __nv_bfloat16 *qh, *ql, *kh, *kl, *vh, *vl, *oh, *ol;
    __nv_bfloat16 *aqh, *aql, *akh, *akl, *avh, *avl;
    __nv_bfloat16 *wqh, *wql, *wkh, *wkl, *wvh, *wvl, *woh, *wol;
    cudaGetSymbolAddress((void**)&qh,  g_qh);  cudaGetSymbolAddress((void**)&ql,  g_ql);
    cudaGetSymbolAddress((void**)&kh,  g_kh);  cudaGetSymbolAddress((void**)&kl,  g_kl);
    cudaGetSymbolAddress((void**)&vh,  g_vh);  cudaGetSymbolAddress((void**)&vl,  g_vl);
    cudaGetSymbolAddress((void**)&oh,  g_oh);  cudaGetSymbolAddress((void**)&ol,  g_ol);
    cudaGetSymbolAddress((void**)&aqh, g_aqh); cudaGetSymbolAddress((void**)&aql, g_aql);
    cudaGetSymbolAddress((void**)&akh, g_akh); cudaGetSymbolAddress((void**)&akl, g_akl);
    cudaGetSymbolAddress((void**)&avh, g_avh); cudaGetSymbolAddress((void**)&avl, g_avl);
    cudaGetSymbolAddress((void**)&wqh, g_wqh); cudaGetSymbolAddress((void**)&wql, g_wql);
    cudaGetSymbolAddress((void**)&wkh, g_wkh); cudaGetSymbolAddress((void**)&wkl, g_wkl);
    cudaGetSymbolAddress((void**)&wvh, g_wvh); cudaGetSymbolAddress((void**)&wvl, g_wvl);
    cudaGetSymbolAddress((void**)&woh, g_woh); cudaGetSymbolAddress((void**)&wol, g_wol);

    cudaFuncSetAttribute(gemm_tc_kernel,
                         cudaFuncAttributeMaxDynamicSharedMemorySize, GEMM_SMEM);
    cudaFuncSetAttribute(attn_mma_kernel,
                         cudaFuncAttributeMaxDynamicSharedMemorySize, ATT_SMEM);

    const int n4a = MROWS * DD / 4;   // 2097152
    const int n4w = DD * DD / 4;      // 262144

    // 1) split activations (q, k, v) — one launch, z=3
    {
        SplitJobs sj{};
        sj.x[0] = (const float4*)query; sj.hi[0] = (__nv_bfloat162*)aqh; sj.lo[0] = (__nv_bfloat162*)aql;
        sj.x[1] = (const float4*)key;   sj.hi[1] = (__nv_bfloat162*)akh; sj.lo[1] = (__nv_bfloat162*)akl;
        sj.x[2] = (const float4*)value; sj.hi[2] = (__nv_bfloat162*)avh; sj.lo[2] = (__nv_bfloat162*)avl;
        split_many_kernel<<<dim3(n4a / 256, 1, 3), 256>>>(sj, n4a);
    }
    // 2) split weights (Wq, Wk, Wv, Wo) — one launch, z=4
    {
        SplitJobs sj{};
        sj.x[0] = (const float4*)Wq; sj.hi[0] = (__nv_bfloat162*)wqh; sj.lo[0] = (__nv_bfloat162*)wql;
        sj.x[1] = (const float4*)Wk; sj.hi[1] = (__nv_bfloat162*)wkh; sj.lo[1] = (__nv_bfloat162*)wkl;
        sj.x[2] = (const float4*)Wv; sj.hi[2] = (__nv_bfloat162*)wvh; sj.lo[2] = (__nv_bfloat162*)wvl;
        sj.x[3] = (const float4*)Wo; sj.hi[3] = (__nv_bfloat162*)woh; sj.lo[3] = (__nv_bfloat162*)wol;
        split_many_kernel<<<dim3(n4w / 256, 1, 4), 256>>>(sj, n4w);
    }
    // 3) fused Q/K/V projections — one launch, z=3 (scale 1/8 folded into Q)
    {
        GemmJobs gj{};
        gj.Ah[0] = aqh; gj.Al[0] = aql; gj.Bh[0] = wqh; gj.Bl[0] = wql;
        gj.bias[0] = bq; gj.Ch[0] = qh; gj.Cl[0] = ql; gj.Cf[0] = nullptr; gj.scale[0] = 0.125f;
        gj.Ah[1] = akh; gj.Al[1] = akl; gj.Bh[1] = wkh; gj.Bl[1] = wkl;
        gj.bias[1] = bk; gj.Ch[1] = kh; gj.Cl[1] = kl; gj.Cf[1] = nullptr; gj.scale[1] = 1.0f;
        gj.Ah[2] = avh; gj.Al[2] = avl; gj.Bh[2] = wvh; gj.Bl[2] = wvl;
        gj.bias[2] = bv; gj.Ch[2] = vh; gj.Cl[2] = vl; gj.Cf[2] = nullptr; gj.scale[2] = 1.0f;
        gemm_tc_kernel<<<dim3(DD / 128, MROWS / 128, 3), 256, GEMM_SMEM>>>(gj);
    }
    // 4) attention -> (oh, ol)
    attn_mma_kernel<<<dim3(SS / 128, BB * HH), 256, ATT_SMEM>>>(qh, ql, kh, kl, vh, vl, oh, ol);
    // 5) output projection -> fp32 d_out
    {
        GemmJobs gj{};
        gj.Ah[0] = oh; gj.Al[0] = ol; gj.Bh[0] = woh; gj.Bl[0] = wol;
        gj.bias[0] = bo; gj.Ch[0] = nullptr; gj.Cl[0] = nullptr; gj.Cf[0] = out; gj.scale[0] = 1.0f;
        gemm_tc_kernel<<<dim3(DD / 128, MROWS / 128, 1), 256, GEMM_SMEM>>>(gj);
    }
}

// round 17
// speedup vs baseline: 1.5834x; 1.0011x over previous
#include <cuda_runtime.h>
#include <cuda_bf16.h>
#include <cstdint>

// Problem constants
#define BB 4
#define SS 2048
#define DD 1024
#define HH 16
#define DKK 64
#define MROWS (BB*SS)          // 8192

// ---------------------------------------------------------------------------
// Scratch (device globals — no allocations allowed)
// ---------------------------------------------------------------------------
__device__ __nv_bfloat16 g_qh[MROWS*DD], g_ql[MROWS*DD];     // Q proj out (pre-scaled 1/8)
__device__ __nv_bfloat16 g_kh[MROWS*DD], g_kl[MROWS*DD];     // K proj out
__device__ __nv_bfloat16 g_vh[MROWS*DD], g_vl[MROWS*DD];     // V proj out
__device__ __nv_bfloat16 g_aqh[MROWS*DD], g_aql[MROWS*DD];   // activation splits
__device__ __nv_bfloat16 g_akh[MROWS*DD], g_akl[MROWS*DD];
__device__ __nv_bfloat16 g_avh[MROWS*DD], g_avl[MROWS*DD];
__device__ __nv_bfloat16 g_oh[MROWS*DD],  g_ol[MROWS*DD];    // attention out
__device__ __nv_bfloat16 g_wqh[DD*DD], g_wql[DD*DD];         // weight splits
__device__ __nv_bfloat16 g_wkh[DD*DD], g_wkl[DD*DD];
__device__ __nv_bfloat16 g_wvh[DD*DD], g_wvl[DD*DD];
__device__ __nv_bfloat16 g_woh[DD*DD], g_wol[DD*DD];

// ---------------------------------------------------------------------------
// Helpers
// ---------------------------------------------------------------------------
__device__ __forceinline__ uint32_t smem_u32(const void* p) {
    uint32_t a;
    asm("{ .reg .u64 t; cvta.to.shared.u64 t, %1; cvt.u32.u64 %0, t; }" : "=r"(a) : "l"(p));
    return a;
}
#define SWZ128(o) ((o) ^ (((o) >> 3) & 0x70))
#define SWZ64(o)  ((o) ^ (((o) >> 3) & 0x30))

#define CP_ASYNC16(dst, src) \
    asm volatile("cp.async.cg.shared.global [%0], [%1], 16;" :: "r"(dst), "l"(src))
#define CP_COMMIT()  asm volatile("cp.async.commit_group;" ::: "memory")
#define CP_WAIT0()   asm volatile("cp.async.wait_group 0;" ::: "memory")
#define CP_WAIT1()   asm volatile("cp.async.wait_group 1;" ::: "memory")

__device__ __forceinline__ void ldsm_x4(uint32_t* r, uint32_t addr) {
    asm volatile("ldmatrix.sync.aligned.m8n8.x4.shared.b16 {%0,%1,%2,%3}, [%4];"
        : "=r"(r[0]), "=r"(r[1]), "=r"(r[2]), "=r"(r[3]) : "r"(addr));
}
__device__ __forceinline__ void ldsm_x4t(uint32_t* r, uint32_t addr) {
    asm volatile("ldmatrix.sync.aligned.m8n8.x4.trans.shared.b16 {%0,%1,%2,%3}, [%4];"
        : "=r"(r[0]), "=r"(r[1]), "=r"(r[2]), "=r"(r[3]) : "r"(addr));
}
__device__ __forceinline__ void mma16816(float* d, const uint32_t* a, const uint32_t* b) {
    asm volatile("mma.sync.aligned.m16n8k16.row.col.f32.bf16.bf16.f32 "
        "{%0,%1,%2,%3}, {%4,%5,%6,%7}, {%8,%9}, {%0,%1,%2,%3};"
        : "+f"(d[0]), "+f"(d[1]), "+f"(d[2]), "+f"(d[3])
        : "r"(a[0]), "r"(a[1]), "r"(a[2]), "r"(a[3]), "r"(b[0]), "r"(b[1]));
}
__device__ __forceinline__ uint32_t packbf2(float x, float y) {
    __nv_bfloat162 t = __floats2bfloat162_rn(x, y);
    return *reinterpret_cast<uint32_t*>(&t);
}

// ---------------------------------------------------------------------------
// Fused split: fp32 -> (bf16 hi, bf16 lo); blockIdx.z selects the job.
// ---------------------------------------------------------------------------
struct SplitJobs {
    const float4*     x[4];
    __nv_bfloat162*   hi[4];
    __nv_bfloat162*   lo[4];
};

__global__ __launch_bounds__(256) void split_many_kernel(SplitJobs jobs, int n4)
{
    const int z = blockIdx.z;
    int i = blockIdx.x * 256 + threadIdx.x;
    if (i >= n4) return;
    float4 v = jobs.x[z][i];
    __nv_bfloat162 h0 = __floats2bfloat162_rn(v.x, v.y);
    __nv_bfloat162 h1 = __floats2bfloat162_rn(v.z, v.w);
    jobs.hi[z][2*i]   = h0;
    jobs.hi[z][2*i+1] = h1;
    jobs.lo[z][2*i]   = __floats2bfloat162_rn(v.x - __low2float(h0), v.y - __high2float(h0));
    jobs.lo[z][2*i+1] = __floats2bfloat162_rn(v.z - __low2float(h1), v.w - __high2float(h1));
}

// ---------------------------------------------------------------------------
// HMMA bf16x3 GEMM (NT), fused over blockIdx.z jobs:
//   acc = sum_k A[i,k]*W[j,k]; out = (acc + bias[j]) * scale
// Output fp32 (Cf) or bf16 hi/lo (Ch,Cl).
// CTA tile 128x128; K-chunk 32 (SW64 swizzle); 3-stage cp.async ring;
// 8 warps = 2(m) x 4(n), warp tile 64x32 via m16n8k16; occupancy 2.
// ---------------------------------------------------------------------------
struct GemmJobs {
    const __nv_bfloat16 *Ah[3], *Al[3], *Bh[3], *Bl[3];
    const float* bias[3];
    __nv_bfloat16 *Ch[3], *Cl[3];
    float* Cf[3];
    float scale[3];
};

#define GTILE  8192                    // one tile chunk: 128 rows x 64B
#define GBUF   (4*GTILE)               // Ah,Al,Bh,Bl = 32 KB
#define GEMM_SMEM (3*GBUF + 1024)      // 3 stages + align pad

__global__ __launch_bounds__(256, 2) void gemm_tc_kernel(GemmJobs j)
{
    extern __shared__ char smem[];
    const uint32_t sbase = (smem_u32(smem) + 1023u) & ~1023u;
    const int z   = blockIdx.z;
    const int tid = threadIdx.x;
    const int wid = tid >> 5;
    const int lid = tid & 31;
    const int wm  = wid >> 2;          // 0..1
    const int wn  = wid & 3;           // 0..3
    const int nBase = blockIdx.x * 128;
    const int mBase = blockIdx.y * 128;

    const uint4* srcs[4] = {
        reinterpret_cast<const uint4*>(j.Ah[z]) + (size_t)mBase * 128,
        reinterpret_cast<const uint4*>(j.Al[z]) + (size_t)mBase * 128,
        reinterpret_cast<const uint4*>(j.Bh[z]) + (size_t)nBase * 128,
        reinterpret_cast<const uint4*>(j.Bl[z]) + (size_t)nBase * 128
    };

    // one K-chunk (32 bf16 = 4 uint4 per row) into stage buffer at bufAddr
    auto load_chunk = [&](int ch, uint32_t bufAddr) {
        const int kq = ch * 4;
#pragma unroll
        for (int t = 0; t < 8; t++) {
            const int tile = t >> 1;
            const int i = tid + (t & 1) * 256;   // 0..511
            const int r = i >> 2, c = i & 3;
            const uint4* src = srcs[tile] + (size_t)r * 128 + kq + c;
            uint32_t dst = bufAddr + tile * GTILE + SWZ64(r * 64 + c * 16);
            CP_ASYNC16(dst, src);
        }
        CP_COMMIT();
    };

    float acc[4][4][4];
#pragma unroll
    for (int mt = 0; mt < 4; mt++)
#pragma unroll
        for (int nt = 0; nt < 4; nt++)
#pragma unroll
            for (int r = 0; r < 4; r++) acc[mt][nt][r] = 0.f;

    load_chunk(0, sbase);
    load_chunk(1, sbase + GBUF);

    // chunk-invariant fragment address components
    const int aRow   = wm * 64 + (lid & 15);
    const int aColH  = (lid >> 4) * 16;
    const int bRow16 = wn * 32 + (lid & 7) + 8 * ((lid >> 4) & 1);
    const int bColH  = ((lid >> 3) & 1) * 16;

    int stage = 0;
#pragma unroll 1
    for (int ch = 0; ch < 32; ch++) {
        if (ch < 30) { CP_WAIT1(); } else { CP_WAIT0(); }
        __syncthreads();
        if (ch < 30) {
            int nst = stage + 2; if (nst >= 3) nst -= 3;
            load_chunk(ch + 2, sbase + nst * GBUF);
        }

        const uint32_t bufAddr = sbase + stage * GBUF;
#pragma unroll
        for (int ks = 0; ks < 2; ks++) {
            uint32_t bh[2][4], bl[2][4];
#pragma unroll
            for (int ntp = 0; ntp < 2; ntp++) {
                uint32_t off = SWZ64((bRow16 + ntp * 16) * 64 + ks * 32 + bColH);
                ldsm_x4(bh[ntp], bufAddr + 2 * GTILE + off);
                ldsm_x4(bl[ntp], bufAddr + 3 * GTILE + off);
            }
#pragma unroll
            for (int mt = 0; mt < 4; mt++) {
                uint32_t ah[4], al[4];
                uint32_t offA = SWZ64((aRow + mt * 16) * 64 + ks * 32 + aColH);
                ldsm_x4(ah, bufAddr + offA);
                ldsm_x4(al, bufAddr + GTILE + offA);
#pragma unroll
                for (int nt = 0; nt < 4; nt++) {
                    const uint32_t* bhp = &bh[nt >> 1][(nt & 1) * 2];
                    const uint32_t* blp = &bl[nt >> 1][(nt & 1) * 2];
                    mma16816(acc[mt][nt], ah, bhp);
                    mma16816(acc[mt][nt], ah, blp);
                    mma16816(acc[mt][nt], al, bhp);
                }
            }
        }
        if (++stage == 3) stage = 0;
    }

    // Epilogue
    const float scale = j.scale[z];
    const float* bias = j.bias[z];
    float* Cf = j.Cf[z];
    __nv_bfloat16* Ch = j.Ch[z];
    __nv_bfloat16* Cl = j.Cl[z];
    const int erow = mBase + wm * 64 + (lid >> 2);
    const int ecolBase = nBase + wn * 32 + 2 * (lid & 3);
#pragma unroll
    for (int nt = 0; nt < 4; nt++) {
        const int col = ecolBase + nt * 8;
        const float b0 = __ldg(bias + col), b1 = __ldg(bias + col + 1);
#pragma unroll
        for (int mt = 0; mt < 4; mt++) {
            const int r0 = erow + mt * 16;
            float v0 = (acc[mt][nt][0] + b0) * scale;
            float v1 = (acc[mt][nt][1] + b1) * scale;
            float v2 = (acc[mt][nt][2] + b0) * scale;
            float v3 = (acc[mt][nt][3] + b1) * scale;
            if (Cf) {
                *reinterpret_cast<float2*>(Cf + (size_t)r0 * DD + col)       = make_float2(v0, v1);
                *reinterpret_cast<float2*>(Cf + (size_t)(r0 + 8) * DD + col) = make_float2(v2, v3);
            } else {
                __nv_bfloat162 h0 = __floats2bfloat162_rn(v0, v1);
                __nv_bfloat162 h1 = __floats2bfloat162_rn(v2, v3);
                *reinterpret_cast<__nv_bfloat162*>(Ch + (size_t)r0 * DD + col)       = h0;
                *reinterpret_cast<__nv_bfloat162*>(Ch + (size_t)(r0 + 8) * DD + col) = h1;
                *reinterpret_cast<__nv_bfloat162*>(Cl + (size_t)r0 * DD + col) =
                    __floats2bfloat162_rn(v0 - __low2float(h0), v1 - __high2float(h0));
                *reinterpret_cast<__nv_bfloat162*>(Cl + (size_t)(r0 + 8) * DD + col) =
                    __floats2bfloat162_rn(v2 - __low2float(h1), v3 - __high2float(h1));
            }
        }
    }
}

// ---------------------------------------------------------------------------
// MMA flash attention. Q pre-scaled by 1/8. All operands bf16 hi/lo in
// [B,S,D] layout (head h = cols h*64..+63). Output -> (Oh,Ol) bf16 hi/lo.
// CTA: 128 query rows x one (b,h); 8 warps x 16 rows; BK=32 keys/iter.
// scores = Qh*Kh + Qh*Kl + Ql*Kh ; PV = Ph*Vh + Ph*Vl + Pl*Vh (fp32 acc).
// K/V fragments via ldmatrix.x4 (two n8 frags per instruction).
// ---------------------------------------------------------------------------
#define KV_BYTES 16384                 // Kh,Kl,Vh,Vl 32x128B each
#define ATT_SMEM (32768 + 2*KV_BYTES + 1024)

__global__ __launch_bounds__(256, 2) void attn_mma_kernel(
    const __nv_bfloat16* __restrict__ Qh, const __nv_bfloat16* __restrict__ Ql,
    const __nv_bfloat16* __restrict__ Kh, const __nv_bfloat16* __restrict__ Kl,
    const __nv_bfloat16* __restrict__ Vh, const __nv_bfloat16* __restrict__ Vl,
    __nv_bfloat16* __restrict__ Oh, __nv_bfloat16* __restrict__ Ol)
{
    extern __shared__ char smem[];
    const uint32_t sb = (smem_u32(smem) + 1023u) & ~1023u;
    const int tid = threadIdx.x;
    const int wid = tid >> 5;
    const int lid = tid & 31;
    const int bh  = blockIdx.y;
    const int b   = bh >> 4, h = bh & 15;
    const int qBase = blockIdx.x * 128;

    const uint32_t QH_OFF = 0, QL_OFF = 16384, KV_OFF = 32768;
    const size_t qOrg = (size_t)(b * SS + qBase) * DD + h * DKK;
    const size_t kOrg = (size_t)(b * SS) * DD + h * DKK;

    // stage Q (hi/lo): 2 x 128 rows x 8 chunks of 16B
    {
#pragma unroll
        for (int jj = 0; jj < 8; jj++) {
            int i  = tid + jj * 256;
            int sp = i >> 10;
            int r  = (i & 1023) >> 3;
            int c  = i & 7;
            const __nv_bfloat16* src = (sp ? Ql : Qh) + qOrg + (size_t)r * DD + c * 8;
            uint32_t dst = sb + (sp ? QL_OFF : QH_OFF) + SWZ128(r * 128 + c * 16);
            CP_ASYNC16(dst, src);
        }
    }
    const __nv_bfloat16* kvsrc[4] = { Kh, Kl, Vh, Vl };
    auto load_kv = [&](int t, int buf) {
        const int r = tid >> 3, c = tid & 7;
        const size_t g = kOrg + (size_t)(t * 32 + r) * DD + c * 8;
        const uint32_t dstb = sb + KV_OFF + buf * KV_BYTES + SWZ128(r * 128 + c * 16);
#pragma unroll
        for (int tile = 0; tile < 4; tile++)
            CP_ASYNC16(dstb + tile * 4096, kvsrc[tile] + g);
        CP_COMMIT();
    };

    load_kv(0, 0);
    CP_WAIT0();
    __syncthreads();

    // Q fragments (persist in registers)
    uint32_t qfh[4][4], qfl[4][4];
    {
        const int aRow = wid * 16 + (lid & 15);
        const int aColH = (lid >> 4) * 16;
#pragma unroll
        for (int ks = 0; ks < 4; ks++) {
            uint32_t off = SWZ128(aRow * 128 + ks * 32 + aColH);
            ldsm_x4(qfh[ks], sb + QH_OFF + off);
            ldsm_x4(qfl[ks], sb + QL_OFF + off);
        }
    }

    float o[8][4];
#pragma unroll
    for (int nt = 0; nt < 8; nt++)
#pragma unroll
        for (int r = 0; r < 4; r++) o[nt][r] = 0.f;
    float m0 = -1e30f, m1 = -1e30f, l0 = 0.f, l1 = 0.f;

    // x4 fragment address components
    const int kRow  = (lid & 7) + 8 * ((lid >> 4) & 1);     // + ntp*16
    const int kColH = ((lid >> 3) & 1) * 16;                // + ks*32
    const int vRow  = (lid & 7) + 8 * ((lid >> 3) & 1);     // + ks*16
    const int vColH = ((lid >> 4) & 1) * 16;                // + ntp*32

#pragma unroll 1
    for (int t = 0; t < SS / 32; t++) {
        const int cur = t & 1;
        if (t < SS / 32 - 1) load_kv(t + 1, cur ^ 1);

        const uint32_t kb = sb + KV_OFF + cur * KV_BYTES;

        // scores: m16 x n32 x k64, bf16x3
        float s[4][4];
#pragma unroll
        for (int nt = 0; nt < 4; nt++)
#pragma unroll
            for (int r = 0; r < 4; r++) s[nt][r] = 0.f;
#pragma unroll
        for (int ks = 0; ks < 4; ks++) {
#pragma unroll
            for (int ntp = 0; ntp < 2; ntp++) {
                uint32_t kbh[4], kbl[4];
                uint32_t off = SWZ128((ntp * 16 + kRow) * 128 + ks * 32 + kColH);
                ldsm_x4(kbh, kb + off);            // Kh tile @ +0
                ldsm_x4(kbl, kb + 4096 + off);     // Kl tile
                mma16816(s[2*ntp],   qfh[ks], &kbh[0]);
                mma16816(s[2*ntp],   qfh[ks], &kbl[0]);
                mma16816(s[2*ntp],   qfl[ks], &kbh[0]);
                mma16816(s[2*ntp+1], qfh[ks], &kbh[2]);
                mma16816(s[2*ntp+1], qfh[ks], &kbl[2]);
                mma16816(s[2*ntp+1], qfl[ks], &kbh[2]);
            }
        }

        // online softmax (rows r=lid>>2 and r+8; cols across lanes lid&3)
        float t0 = -1e30f, t1 = -1e30f;
#pragma unroll
        for (int nt = 0; nt < 4; nt++) {
            t0 = fmaxf(t0, fmaxf(s[nt][0], s[nt][1]));
            t1 = fmaxf(t1, fmaxf(s[nt][2], s[nt][3]));
        }
        t0 = fmaxf(t0, __shfl_xor_sync(0xffffffffu, t0, 1));
        t0 = fmaxf(t0, __shfl_xor_sync(0xffffffffu, t0, 2));
        t1 = fmaxf(t1, __shfl_xor_sync(0xffffffffu, t1, 1));
        t1 = fmaxf(t1, __shfl_xor_sync(0xffffffffu, t1, 2));
        const float mn0 = fmaxf(m0, t0), mn1 = fmaxf(m1, t1);
        const float c0 = __expf(m0 - mn0), c1 = __expf(m1 - mn1);
        m0 = mn0; m1 = mn1;

        uint32_t aPh[2][4], aPl[2][4];
        float rs0 = 0.f, rs1 = 0.f;
#pragma unroll
        for (int nt = 0; nt < 4; nt++) {
            float p0 = __expf(s[nt][0] - m0);
            float p1 = __expf(s[nt][1] - m0);
            float p2 = __expf(s[nt][2] - m1);
            float p3 = __expf(s[nt][3] - m1);
            rs0 += p0 + p1; rs1 += p2 + p3;
            const int ks = nt >> 1, pos = (nt & 1) * 2;
            __nv_bfloat162 hA = __floats2bfloat162_rn(p0, p1);
            __nv_bfloat162 hB = __floats2bfloat162_rn(p2, p3);
            aPh[ks][pos]     = *reinterpret_cast<uint32_t*>(&hA);
            aPh[ks][pos + 1] = *reinterpret_cast<uint32_t*>(&hB);
            aPl[ks][pos]     = packbf2(p0 - __low2float(hA), p1 - __high2float(hA));
            aPl[ks][pos + 1] = packbf2(p2 - __low2float(hB), p3 - __high2float(hB));
        }
        rs0 += __shfl_xor_sync(0xffffffffu, rs0, 1);
        rs0 += __shfl_xor_sync(0xffffffffu, rs0, 2);
        rs1 += __shfl_xor_sync(0xffffffffu, rs1, 1);
        rs1 += __shfl_xor_sync(0xffffffffu, rs1, 2);
        l0 = l0 * c0 + rs0;
        l1 = l1 * c1 + rs1;

#pragma unroll
        for (int nt = 0; nt < 8; nt++) {
            o[nt][0] *= c0; o[nt][1] *= c0;
            o[nt][2] *= c1; o[nt][3] *= c1;
        }

        // PV: m16 x n64 x k32, bf16x3 (V via ldmatrix.x4.trans)
#pragma unroll
        for (int ks = 0; ks < 2; ks++) {
#pragma unroll
            for (int ntp = 0; ntp < 4; ntp++) {
                uint32_t vbh[4], vbl[4];
                uint32_t off = SWZ128((ks * 16 + vRow) * 128 + ntp * 32 + vColH);
                ldsm_x4t(vbh, kb + 8192 + off);     // Vh tile
                ldsm_x4t(vbl, kb + 12288 + off);    // Vl tile
                mma16816(o[2*ntp],   aPh[ks], &vbh[0]);
                mma16816(o[2*ntp],   aPh[ks], &vbl[0]);
                mma16816(o[2*ntp],   aPl[ks], &vbh[0]);
                mma16816(o[2*ntp+1], aPh[ks], &vbh[2]);
                mma16816(o[2*ntp+1], aPh[ks], &vbl[2]);
                mma16816(o[2*ntp+1], aPl[ks], &vbh[2]);
            }
        }

        CP_WAIT0();
        __syncthreads();
    }

    // epilogue: normalize, split to bf16 hi/lo, write [B,S,D]
    const float i0 = 1.f / l0, i1 = 1.f / l1;
    const size_t row0 = (size_t)(b * SS + qBase + wid * 16 + (lid >> 2));
    const int colBase = h * DKK + 2 * (lid & 3);
#pragma unroll
    for (int nt = 0; nt < 8; nt++) {
        const int col = colBase + nt * 8;
        float v0 = o[nt][0] * i0, v1 = o[nt][1] * i0;
        float v2 = o[nt][2] * i1, v3 = o[nt][3] * i1;
        __nv_bfloat162 h0 = __floats2bfloat162_rn(v0, v1);
        __nv_bfloat162 h1 = __floats2bfloat162_rn(v2, v3);
        *reinterpret_cast<__nv_bfloat162*>(Oh + row0 * DD + col)       = h0;
        *reinterpret_cast<__nv_bfloat162*>(Oh + (row0 + 8) * DD + col) = h1;
        *reinterpret_cast<__nv_bfloat162*>(Ol + row0 * DD + col) =
            __floats2bfloat162_rn(v0 - __low2float(h0), v1 - __high2float(h0));
        *reinterpret_cast<__nv_bfloat162*>(Ol + (row0 + 8) * DD + col) =
            __floats2bfloat162_rn(v2 - __low2float(h1), v3 - __high2float(h1));
    }
}

// ---------------------------------------------------------------------------
// kernel_launch
// ---------------------------------------------------------------------------
extern "C" void kernel_launch(void* const* d_in, const int* in_sizes, int n_in,
                              void* d_out, int out_size)
{
    const float* query = (const float*)d_in[0];
    const float* key   = (const float*)d_in[1];
    const float* value = (const float*)d_in[2];
    const float* Wq    = (const float*)d_in[3];
    const float* bq    = (const float*)d_in[4];
    const float* Wk    = (const float*)d_in[5];
    const float* bk    = (const float*)d_in[6];
    const float* Wv    = (const float*)d_in[7];
    const float* bv    = (const float*)d_in[8];
    const float* Wo    = (const float*)d_in[9];
    const float* bo    = (const float*)d_in[10];
    float* out = (float*)d_out;

    __nv_bfloat16 *qh, *ql, *kh, *kl, *vh, *vl, *oh, *ol;
    __nv_bfloat16 *aqh, *aql, *akh, *akl, *avh, *avl;
    __nv_bfloat16 *wqh, *wql, *wkh, *wkl, *wvh, *wvl, *woh, *wol;
    cudaGetSymbolAddress((void**)&qh,  g_qh);  cudaGetSymbolAddress((void**)&ql,  g_ql);
    cudaGetSymbolAddress((void**)&kh,  g_kh);  cudaGetSymbolAddress((void**)&kl,  g_kl);
    cudaGetSymbolAddress((void**)&vh,  g_vh);  cudaGetSymbolAddress((void**)&vl,  g_vl);
    cudaGetSymbolAddress((void**)&oh,  g_oh);  cudaGetSymbolAddress((void**)&ol,  g_ol);
    cudaGetSymbolAddress((void**)&aqh, g_aqh); cudaGetSymbolAddress((void**)&aql, g_aql);
    cudaGetSymbolAddress((void**)&akh, g_akh); cudaGetSymbolAddress((void**)&akl, g_akl);
    cudaGetSymbolAddress((void**)&avh, g_avh); cudaGetSymbolAddress((void**)&avl, g_avl);
    cudaGetSymbolAddress((void**)&wqh, g_wqh); cudaGetSymbolAddress((void**)&wql, g_wql);
    cudaGetSymbolAddress((void**)&wkh, g_wkh); cudaGetSymbolAddress((void**)&wkl, g_wkl);
    cudaGetSymbolAddress((void**)&wvh, g_wvh); cudaGetSymbolAddress((void**)&wvl, g_wvl);
    cudaGetSymbolAddress((void**)&woh, g_woh); cudaGetSymbolAddress((void**)&wol, g_wol);

    cudaFuncSetAttribute(gemm_tc_kernel,
                         cudaFuncAttributeMaxDynamicSharedMemorySize, GEMM_SMEM);
    cudaFuncSetAttribute(attn_mma_kernel,
                         cudaFuncAttributeMaxDynamicSharedMemorySize, ATT_SMEM);

    const int n4a = MROWS * DD / 4;   // 2097152
    const int n4w = DD * DD / 4;      // 262144

    // 1) split activations (q, k, v) — one launch, z=3
    {
        SplitJobs sj{};
        sj.x[0] = (const float4*)query; sj.hi[0] = (__nv_bfloat162*)aqh; sj.lo[0] = (__nv_bfloat162*)aql;
        sj.x[1] = (const float4*)key;   sj.hi[1] = (__nv_bfloat162*)akh; sj.lo[1] = (__nv_bfloat162*)akl;
        sj.x[2] = (const float4*)value; sj.hi[2] = (__nv_bfloat162*)avh; sj.lo[2] = (__nv_bfloat162*)avl;
        split_many_kernel<<<dim3(n4a / 256, 1, 3), 256>>>(sj, n4a);
    }
    // 2) split weights (Wq, Wk, Wv, Wo) — one launch, z=4
    {
        SplitJobs sj{};
        sj.x[0] = (const float4*)Wq; sj.hi[0] = (__nv_bfloat162*)wqh; sj.lo[0] = (__nv_bfloat162*)wql;
        sj.x[1] = (const float4*)Wk; sj.hi[1] = (__nv_bfloat162*)wkh; sj.lo[1] = (__nv_bfloat162*)wkl;
        sj.x[2] = (const float4*)Wv; sj.hi[2] = (__nv_bfloat162*)wvh; sj.lo[2] = (__nv_bfloat162*)wvl;
        sj.x[3] = (const float4*)Wo; sj.hi[3] = (__nv_bfloat162*)woh; sj.lo[3] = (__nv_bfloat162*)wol;
        split_many_kernel<<<dim3(n4w / 256, 1, 4), 256>>>(sj, n4w);
    }
    // 3) fused Q/K/V projections — one launch, z=3 (scale 1/8 folded into Q)
    {
        GemmJobs gj{};
        gj.Ah[0] = aqh; gj.Al[0] = aql; gj.Bh[0] = wqh; gj.Bl[0] = wql;
        gj.bias[0] = bq; gj.Ch[0] = qh; gj.Cl[0] = ql; gj.Cf[0] = nullptr; gj.scale[0] = 0.125f;
        gj.Ah[1] = akh; gj.Al[1] = akl; gj.Bh[1] = wkh; gj.Bl[1] = wkl;
        gj.bias[1] = bk; gj.Ch[1] = kh; gj.Cl[1] = kl; gj.Cf[1] = nullptr; gj.scale[1] = 1.0f;
        gj.Ah[2] = avh; gj.Al[2] = avl; gj.Bh[2] = wvh; gj.Bl[2] = wvl;
        gj.bias[2] = bv; gj.Ch[2] = vh; gj.Cl[2] = vl; gj.Cf[2] = nullptr; gj.scale[2] = 1.0f;
        gemm_tc_kernel<<<dim3(DD / 128, MROWS / 128, 3), 256, GEMM_SMEM>>>(gj);
    }
    // 4) attention -> (oh, ol)
    attn_mma_kernel<<<dim3(SS / 128, BB * HH), 256, ATT_SMEM>>>(qh, ql, kh, kl, vh, vl, oh, ol);
    // 5) output projection -> fp32 d_out
    {
        GemmJobs gj{};
        gj.Ah[0] = oh; gj.Al[0] = ol; gj.Bh[0] = woh; gj.Bl[0] = wol;
        gj.bias[0] = bo; gj.Ch[0] = nullptr; gj.Cl[0] = nullptr; gj.Cf[0] = out; gj.scale[0] = 1.0f;
        gemm_tc_kernel<<<dim3(DD / 128, MROWS / 128, 1), 256, GEMM_SMEM>>>(gj);
    }
}